// round 13
// baseline (speedup 1.0000x reference)
#include <cuda_runtime.h>
#include <cuda_bf16.h>
#include <math.h>
#include <stdint.h>

#define NB 2
#define NT 2048
#define NC 1024
#define NH 16
#define DHD 64
#define NHID 32
#define N3C 3072
#define NM 4096
#define NDIST 4095
#define MMK 1024
#define BM 128
#define BN 128
#define BKC 32
#define NCHUNK (MMK/BKC)
#define LOG2E 1.4426950408889634f

// ---------------- statics: same 67.2MB footprint as passing R6-R11 ---------------
__device__ __align__(16) __nv_bfloat16 g_qhi[NB*NH*NT*DHD];  // [bh][t][dh], pre-scaled log2e/8
__device__ __align__(16) __nv_bfloat16 g_qlo[NB*NH*NT*DHD];
__device__ __align__(16) __nv_bfloat16 g_khi[NB*NH*NT*DHD];
__device__ __align__(16) __nv_bfloat16 g_klo[NB*NH*NT*DHD];
__device__ __align__(16) __nv_bfloat16 g_vhi[NB*NH*NT*DHD];
__device__ __align__(16) __nv_bfloat16 g_vlo[NB*NH*NT*DHD];
// g_ctx doubles as: (a) xhi/xlo bf16 scratch for mm<0>, (b) fp32 attention output.
__device__ __align__(16) float g_ctx[NM*NC];
__device__ float g_bias[NH*NDIST];          // pre-scaled by log2e

// ================= PTX helpers ==================================================
__device__ __forceinline__ uint32_t s2u(const void* p) {
    uint32_t a;
    asm("{ .reg .u64 t; cvta.to.shared.u64 t, %1; cvt.u32.u64 %0, t; }" : "=r"(a) : "l"(p));
    return a;
}
#define CP_ASYNC16(dst, src) \
    asm volatile("cp.async.cg.shared.global [%0], [%1], 16;" :: "r"(dst), "l"(src))
#define CP_COMMIT() asm volatile("cp.async.commit_group;" ::: "memory")
#define CP_WAIT0()  asm volatile("cp.async.wait_group 0;" ::: "memory")

#define LDM_X4(r0,r1,r2,r3,addr) \
    asm volatile("ldmatrix.sync.aligned.m8n8.x4.shared.b16 {%0,%1,%2,%3}, [%4];" \
        : "=r"(r0),"=r"(r1),"=r"(r2),"=r"(r3) : "r"(addr))
#define LDM_X4T(r0,r1,r2,r3,addr) \
    asm volatile("ldmatrix.sync.aligned.m8n8.x4.trans.shared.b16 {%0,%1,%2,%3}, [%4];" \
        : "=r"(r0),"=r"(r1),"=r"(r2),"=r"(r3) : "r"(addr))
#define LDM_X2T(r0,r1,addr) \
    asm volatile("ldmatrix.sync.aligned.m8n8.x2.trans.shared.b16 {%0,%1}, [%2];" \
        : "=r"(r0),"=r"(r1) : "r"(addr))

#define MMA_BF16(c0,c1,c2,c3,a0,a1,a2,a3,b0,b1) \
    asm volatile("mma.sync.aligned.m16n8k16.row.col.f32.bf16.bf16.f32 " \
                 "{%0,%1,%2,%3}, {%4,%5,%6,%7}, {%8,%9}, {%0,%1,%2,%3};" \
                 : "+f"(c0), "+f"(c1), "+f"(c2), "+f"(c3) \
                 : "r"(a0), "r"(a1), "r"(a2), "r"(a3), "r"(b0), "r"(b1))

#define CVT_HILO(x, y, hi, lo) do{ \
    asm("cvt.rn.bf16x2.f32 %0, %1, %2;" : "=r"(hi) : "f"(y), "f"(x)); \
    float _lx = (x) - __uint_as_float((hi) << 16); \
    float _ly = (y) - __uint_as_float((hi) & 0xFFFF0000u); \
    asm("cvt.rn.bf16x2.f32 %0, %1, %2;" : "=r"(lo) : "f"(_ly), "f"(_lx)); \
}while(0)

#define EX2(d, s) asm("ex2.approx.ftz.f32 %0, %1;" : "=f"(d) : "f"(s))

// ---------------- RPE bias table (pre-scaled by log2e) --------------------------
__global__ void rpe_kernel(const float* __restrict__ w1, const float* __restrict__ b1,
                           const float* __restrict__ w2, const float* __restrict__ b2)
{
    int d = blockIdx.x * blockDim.x + threadIdx.x;
    if (d >= NDIST) return;
    float rel = (float)(d - (NT - 1));
    float sgn = (rel > 0.f) ? 1.f : ((rel < 0.f) ? -1.f : 0.f);
    float x = sgn * log1pf(fabsf(rel));
    float h[NHID];
#pragma unroll
    for (int j = 0; j < NHID; j++)
        h[j] = fmaxf(fmaf(x, __ldg(&w1[j]), __ldg(&b1[j])), 0.f);
#pragma unroll
    for (int hd = 0; hd < NH; hd++) {
        float acc = __ldg(&b2[hd]);
#pragma unroll
        for (int j = 0; j < NHID; j++)
            acc = fmaf(h[j], __ldg(&w2[j*NH + hd]), acc);
        g_bias[hd*NDIST + d] = acc * LOG2E;
    }
}

// ---------------- x -> bf16 hi/lo (into g_ctx scratch) ---------------------------
__global__ void conv_x_kernel(const float* __restrict__ x) {
    __nv_bfloat16* xhi = (__nv_bfloat16*)g_ctx;
    __nv_bfloat16* xlo = xhi + (long)NM * NC;
    long i = (long)(blockIdx.x * blockDim.x + threadIdx.x) * 4;
    float4 v = *(const float4*)&x[i];
    uint32_t h01, l01, h23, l23;
    CVT_HILO(v.x, v.y, h01, l01);
    CVT_HILO(v.z, v.w, h23, l23);
    *(uint2*)&xhi[i] = make_uint2(h01, h23);
    *(uint2*)&xlo[i] = make_uint2(l01, l23);
}

// ---------------- mma.sync bf16 3-term split GEMM, 512 threads / 16 warps --------
// Race-fixed pipeline: CP_A(i+1) is issued AFTER __syncthreads (all readers of its
// destination stage provably done), wait precedes the barrier.
#define RS_A 80
#define A_TILE_B (128 * RS_A)
#define RS_B 272
#define B_TILE_B (32 * RS_B)
#define STAGE_B (2*A_TILE_B + 2*B_TILE_B)
#define OFF_AHI 0
#define OFF_ALO A_TILE_B
#define OFF_BHI (2*A_TILE_B)
#define OFF_BLO (2*A_TILE_B + B_TILE_B)
#define MM_SMEM_BYTES (2 * STAGE_B)

template<int MODE>
__global__ void __launch_bounds__(512, 1) mm_kernel(
    const float* __restrict__ Ain, const float* __restrict__ Bin, int ldb,
    const float* __restrict__ bias, float* __restrict__ outp)
{
    extern __shared__ __align__(16) char dsm[];
    const float* __restrict__ Ap = (MODE == 0) ? Ain : g_ctx;
    const __nv_bfloat16* __restrict__ Axhi = (const __nv_bfloat16*)g_ctx;
    const __nv_bfloat16* __restrict__ Axlo = Axhi + (long)NM * NC;

    const int tid = threadIdx.x;
    const int wid = tid >> 5, lane = tid & 31;
    const int bm = blockIdx.y * BM, bn = blockIdx.x * BN;
    const int wm = (wid & 3) * 32, wn = (wid >> 2) * 32;
    const uint32_t sbase = s2u(dsm);

    float acc[2][4][4];
#pragma unroll
    for (int mi = 0; mi < 2; mi++)
#pragma unroll
        for (int ni = 0; ni < 4; ni++)
#pragma unroll
            for (int r = 0; r < 4; r++) acc[mi][ni][r] = 0.f;

    // per-thread geometry: A quarter-rows (8 floats), B eighth-rows (8 floats)
    const float* __restrict__ aptr = Ap + (long)(bm + (tid >> 2)) * MMK + (tid & 3) * 8;
    const float* __restrict__ bptr = Bin + (long)(tid >> 4) * ldb + bn + (tid & 15) * 8;
    const int ar = tid >> 2, ah = tid & 3;   // MODE 0 A cp.async geometry

#define CP_A(chunk, stage) do { \
    long off_ = (long)(bm + ar) * MMK + (chunk) * BKC + ah * 8; \
    uint32_t d_ = sbase + (stage) * STAGE_B + ar * RS_A + ah * 16; \
    CP_ASYNC16(d_ + OFF_AHI, Axhi + off_); \
    CP_ASYNC16(d_ + OFF_ALO, Axlo + off_); \
    CP_COMMIT(); \
} while(0)

    float4 va0, va1, vb0, vb1;
#define LOADC(k0) do { \
    if (MODE == 1) { \
        const float* _a = aptr + (k0); \
        va0 = *(const float4*)(_a + 0);  va1 = *(const float4*)(_a + 4); \
    } \
    const float* _b = bptr + (long)(k0) * ldb; \
    vb0 = *(const float4*)(_b + 0);  vb1 = *(const float4*)(_b + 4); \
} while(0)

    if (MODE == 0) CP_A(0, 0);
    LOADC(0);

    const int laneA_row = lane & 15, laneA_half = (lane >> 4) * 16;
    const uint32_t laneB_row = (lane & 7) + ((lane >> 3) & 1) * 8;

    for (int i = 0; i < NCHUNK; i++) {
        const int buf = i & 1;
        char* sp = dsm + buf * STAGE_B;
        if (MODE == 1) {
            char* pa = sp + (tid >> 2) * RS_A + (tid & 3) * 16;
            uint32_t h0,h1,h2,h3, l0,l1,l2,l3;
            CVT_HILO(va0.x, va0.y, h0, l0);  CVT_HILO(va0.z, va0.w, h1, l1);
            CVT_HILO(va1.x, va1.y, h2, l2);  CVT_HILO(va1.z, va1.w, h3, l3);
            *(uint4*)(pa + OFF_AHI) = make_uint4(h0, h1, h2, h3);
            *(uint4*)(pa + OFF_ALO) = make_uint4(l0, l1, l2, l3);
        }
        {
            char* pb = sp + (tid >> 4) * RS_B + (tid & 15) * 16;
            uint32_t h0,h1,h2,h3, l0,l1,l2,l3;
            CVT_HILO(vb0.x, vb0.y, h0, l0);  CVT_HILO(vb0.z, vb0.w, h1, l1);
            CVT_HILO(vb1.x, vb1.y, h2, l2);  CVT_HILO(vb1.z, vb1.w, h3, l3);
            *(uint4*)(pb + OFF_BHI) = make_uint4(h0, h1, h2, h3);
            *(uint4*)(pb + OFF_BLO) = make_uint4(l0, l1, l2, l3);
        }
        // wait for THIS stage's A dma (MODE 0) before the barrier, so its data is
        // visible to all threads after the barrier.
        if (MODE == 0) CP_WAIT0();
        __syncthreads();
        // NOW every thread has finished MMA(i-1) (the last reader of stage buf^1):
        // safe to start the async fill of stage buf^1 for chunk i+1.
        if (MODE == 0 && i + 1 < NCHUNK) CP_A(i + 1, buf ^ 1);
        if (i + 1 < NCHUNK) LOADC((i + 1) * BKC);

        const uint32_t stb  = sbase + buf * STAGE_B;
        const uint32_t sAhi = stb + OFF_AHI;
        const uint32_t sAlo = stb + OFF_ALO;
        const uint32_t sBhi = stb + OFF_BHI;
        const uint32_t sBlo = stb + OFF_BLO;

#pragma unroll
        for (int kk = 0; kk < 2; kk++) {
            const uint32_t koffA = kk * 32;
            const uint32_t browB = (kk * 16 + laneB_row) * RS_B;
            uint32_t bh0,bh1,bh2,bh3,bh4,bh5,bh6,bh7;
            uint32_t bl0,bl1,bl2,bl3,bl4,bl5,bl6,bl7;
            LDM_X2T(bh0, bh1, sBhi + browB + (wn + 0*8) * 2);
            LDM_X2T(bh2, bh3, sBhi + browB + (wn + 1*8) * 2);
            LDM_X2T(bh4, bh5, sBhi + browB + (wn + 2*8) * 2);
            LDM_X2T(bh6, bh7, sBhi + browB + (wn + 3*8) * 2);
            LDM_X2T(bl0, bl1, sBlo + browB + (wn + 0*8) * 2);
            LDM_X2T(bl2, bl3, sBlo + browB + (wn + 1*8) * 2);
            LDM_X2T(bl4, bl5, sBlo + browB + (wn + 2*8) * 2);
            LDM_X2T(bl6, bl7, sBlo + browB + (wn + 3*8) * 2);
#pragma unroll
            for (int mi = 0; mi < 2; mi++) {
                uint32_t a0, a1, a2, a3;
                uint32_t aa = sAhi + (wm + mi*16 + laneA_row) * RS_A + laneA_half + koffA;
                LDM_X4(a0, a1, a2, a3, aa);
                MMA_BF16(acc[mi][0][0],acc[mi][0][1],acc[mi][0][2],acc[mi][0][3], a0,a1,a2,a3, bh0,bh1);
                MMA_BF16(acc[mi][1][0],acc[mi][1][1],acc[mi][1][2],acc[mi][1][3], a0,a1,a2,a3, bh2,bh3);
                MMA_BF16(acc[mi][2][0],acc[mi][2][1],acc[mi][2][2],acc[mi][2][3], a0,a1,a2,a3, bh4,bh5);
                MMA_BF16(acc[mi][3][0],acc[mi][3][1],acc[mi][3][2],acc[mi][3][3], a0,a1,a2,a3, bh6,bh7);
                MMA_BF16(acc[mi][0][0],acc[mi][0][1],acc[mi][0][2],acc[mi][0][3], a0,a1,a2,a3, bl0,bl1);
                MMA_BF16(acc[mi][1][0],acc[mi][1][1],acc[mi][1][2],acc[mi][1][3], a0,a1,a2,a3, bl2,bl3);
                MMA_BF16(acc[mi][2][0],acc[mi][2][1],acc[mi][2][2],acc[mi][2][3], a0,a1,a2,a3, bl4,bl5);
                MMA_BF16(acc[mi][3][0],acc[mi][3][1],acc[mi][3][2],acc[mi][3][3], a0,a1,a2,a3, bl6,bl7);
            }
#pragma unroll
            for (int mi = 0; mi < 2; mi++) {
                uint32_t a0, a1, a2, a3;
                uint32_t aa = sAlo + (wm + mi*16 + laneA_row) * RS_A + laneA_half + koffA;
                LDM_X4(a0, a1, a2, a3, aa);
                MMA_BF16(acc[mi][0][0],acc[mi][0][1],acc[mi][0][2],acc[mi][0][3], a0,a1,a2,a3, bh0,bh1);
                MMA_BF16(acc[mi][1][0],acc[mi][1][1],acc[mi][1][2],acc[mi][1][3], a0,a1,a2,a3, bh2,bh3);
                MMA_BF16(acc[mi][2][0],acc[mi][2][1],acc[mi][2][2],acc[mi][2][3], a0,a1,a2,a3, bh4,bh5);
                MMA_BF16(acc[mi][3][0],acc[mi][3][1],acc[mi][3][2],acc[mi][3][3], a0,a1,a2,a3, bh6,bh7);
            }
        }
    }
#undef LOADC
#undef CP_A

    const int lane4 = lane >> 2, lane2 = (lane & 3) * 2;
#pragma unroll
    for (int mi = 0; mi < 2; mi++) {
        int r0 = bm + wm + mi*16 + lane4;
        int r1 = r0 + 8;
#pragma unroll
        for (int ni = 0; ni < 4; ni++) {
            int ng = bn + wn + ni*8 + lane2;
            float bz0 = bias[ng], bz1 = bias[ng + 1];
            float c0 = acc[mi][ni][0] + bz0, c1 = acc[mi][ni][1] + bz1;
            float c2 = acc[mi][ni][2] + bz0, c3 = acc[mi][ni][3] + bz1;
            if (MODE == 1) {
                float2 v0 = {c0, c1}, v1 = {c2, c3};
                *(float2*)&outp[(long)r0 * NC + ng] = v0;
                *(float2*)&outp[(long)r1 * NC + ng] = v1;
            } else {
                const int sel = bn >> 10;
                int n = ng & (NC - 1);
                int head = n >> 6, dh = n & (DHD - 1);
                int b0 = r0 >> 11, t0 = r0 & (NT - 1);
                int b1 = r1 >> 11, t1 = r1 & (NT - 1);
                if (sel == 0) {
                    const float qs = 0.125f * LOG2E;
                    c0 *= qs; c1 *= qs; c2 *= qs; c3 *= qs;
                }
                uint32_t hi0, lo0, hi1, lo1;
                CVT_HILO(c0, c1, hi0, lo0);
                CVT_HILO(c2, c3, hi1, lo1);
                __nv_bfloat16* dhi = (sel == 0) ? g_qhi : (sel == 1) ? g_khi : g_vhi;
                __nv_bfloat16* dlo = (sel == 0) ? g_qlo : (sel == 1) ? g_klo : g_vlo;
                long e0 = ((long)(((b0 << 4) + head) * NT + t0)) * DHD + dh;
                long e1 = ((long)(((b1 << 4) + head) * NT + t1)) * DHD + dh;
                *(uint32_t*)(dhi + e0) = hi0;  *(uint32_t*)(dlo + e0) = lo0;
                *(uint32_t*)(dhi + e1) = hi1;  *(uint32_t*)(dlo + e1) = lo1;
            }
        }
    }
}

// ---------------- tensor-core flash attention, BQ=256, 16 warps (= R11) ---------
#define RS_F 144
#define QTILE_B (256 * RS_F)
#define KVT_B   (64 * RS_F)
#define STAGE_F (4 * KVT_B)
#define OFF_Q    0
#define OFF_ST   (2 * QTILE_B)
#define OFF_BAND (OFF_ST + 2 * STAGE_F)
#define FL_SMEM  (OFF_BAND + 2 * 336 * 8)

__global__ void __launch_bounds__(512, 1) flash_kernel()
{
    extern __shared__ __align__(16) char fsm[];
    const int tid = threadIdx.x, wid = tid >> 5, lane = tid & 31;
    const int bh = blockIdx.y, h = bh & (NH - 1), b = bh >> 4;
    const int q0 = blockIdx.x * 256;
    const uint32_t sb = s2u(fsm);
    const long kvbase = (long)bh * NT * DHD;
    const int hb = h * NDIST;
    float2* bandp = (float2*)(fsm + OFF_BAND);

    {
        int a = tid >> 8, row = tid & 255;
        const uint4* src = (const uint4*)((a ? g_qlo : g_qhi) + kvbase + (long)(q0 + row) * DHD);
        uint4* dst = (uint4*)(fsm + OFF_Q + a * QTILE_B + row * RS_F);
#pragma unroll
        for (int u = 0; u < 8; u++) dst[u] = src[u];
    }

#define CP_STAGE(tile, buf) do { \
    int a_ = tid >> 7; int r2_ = tid & 127; int row_ = r2_ >> 1; \
    const __nv_bfloat16* g_ = (a_ == 0) ? g_khi : (a_ == 1) ? g_klo : (a_ == 2) ? g_vhi : g_vlo; \
    const char* src_ = (const char*)(g_ + kvbase + (long)((tile) * 64 + row_) * DHD) + (r2_ & 1) * 64; \
    uint32_t dst_ = sb + OFF_ST + (buf) * STAGE_F + a_ * KVT_B + row_ * RS_F + (r2_ & 1) * 64; \
    CP_ASYNC16(dst_ +  0, src_ +  0); CP_ASYNC16(dst_ + 16, src_ + 16); \
    CP_ASYNC16(dst_ + 32, src_ + 32); CP_ASYNC16(dst_ + 48, src_ + 48); \
} while(0)

#define BAND_W(tile, buf) do { \
    int base_ = q0 - (tile) * 64 + 1984; \
    if (tid < 319) { \
        int d0_ = base_ + tid; int d1_ = d0_ - 1; if (d1_ < 0) d1_ = 0; \
        bandp[(buf) * 336 + tid] = make_float2(g_bias[hb + d0_], g_bias[hb + d1_]); \
    } \
} while(0)

    CP_STAGE(0, 0);
    CP_COMMIT();
    BAND_W(0, 0);

    float o[8][4];
#pragma unroll
    for (int nt = 0; nt < 8; nt++)
#pragma unroll
        for (int r = 0; r < 4; r++) o[nt][r] = 0.f;
    float rm0 = -1e30f, rm1 = -1e30f, rl0 = 0.f, rl1 = 0.f;

    const int g = lane >> 2, t2 = (lane & 3) * 2;
    const int krow_lane = ((lane >> 4) & 1) * 8 + (lane & 7);
    const int kbyte     = ((lane >> 3) & 1) * 16;
    const int vrow_lane = ((lane >> 3) & 1) * 8 + (lane & 7);
    const int vcol      = (lane >> 4);
    const int qrow_lane = lane & 15;
    const int qbyte     = (lane >> 4) * 16;
    const int e0 = wid * 16 + g + 63 - t2;

    for (int i = 0; i < 32; i++) {
        const int buf = i & 1;
        CP_WAIT0();
        __syncthreads();
        if (i + 1 < 32) {
            CP_STAGE(i + 1, buf ^ 1);
            CP_COMMIT();
            BAND_W(i + 1, buf ^ 1);
        }

        const uint32_t stg  = sb + OFF_ST + buf * STAGE_F;
        const uint32_t sKhi = stg;
        const uint32_t sVhi = stg + 2 * KVT_B;

        float s[8][4];
#pragma unroll
        for (int nt = 0; nt < 8; nt++)
#pragma unroll
            for (int r = 0; r < 4; r++) s[nt][r] = 0.f;

#pragma unroll
        for (int kt = 0; kt < 4; kt++) {
            uint32_t qh0, qh1, qh2, qh3, ql0, ql1, ql2, ql3;
            uint32_t qa = sb + OFF_Q + (wid*16 + qrow_lane) * RS_F + qbyte + kt * 32;
            LDM_X4(qh0, qh1, qh2, qh3, qa);
            LDM_X4(ql0, ql1, ql2, ql3, qa + QTILE_B);
#pragma unroll
            for (int p = 0; p < 4; p++) {
                uint32_t k0,k1,k2,k3, n0,n1,n2,n3;
                uint32_t ka = sKhi + (p*16 + krow_lane) * RS_F + kbyte + kt * 32;
                LDM_X4(k0, k1, k2, k3, ka);
                LDM_X4(n0, n1, n2, n3, ka + KVT_B);
                MMA_BF16(s[2*p][0],s[2*p][1],s[2*p][2],s[2*p][3],
                         qh0,qh1,qh2,qh3, k0,k1);
                MMA_BF16(s[2*p][0],s[2*p][1],s[2*p][2],s[2*p][3],
                         qh0,qh1,qh2,qh3, n0,n1);
                MMA_BF16(s[2*p][0],s[2*p][1],s[2*p][2],s[2*p][3],
                         ql0,ql1,ql2,ql3, k0,k1);
                MMA_BF16(s[2*p+1][0],s[2*p+1][1],s[2*p+1][2],s[2*p+1][3],
                         qh0,qh1,qh2,qh3, k2,k3);
                MMA_BF16(s[2*p+1][0],s[2*p+1][1],s[2*p+1][2],s[2*p+1][3],
                         qh0,qh1,qh2,qh3, n2,n3);
                MMA_BF16(s[2*p+1][0],s[2*p+1][1],s[2*p+1][2],s[2*p+1][3],
                         ql0,ql1,ql2,ql3, k2,k3);
            }
        }

        const float2* bd = bandp + buf * 336;
        float mx0 = -1e30f, mx1 = -1e30f;
#pragma unroll
        for (int nt = 0; nt < 8; nt++) {
            float2 b0v = bd[e0 - 8*nt];
            float2 b1v = bd[e0 + 8 - 8*nt];
            s[nt][0] += b0v.x;  s[nt][1] += b0v.y;
            s[nt][2] += b1v.x;  s[nt][3] += b1v.y;
            mx0 = fmaxf(mx0, fmaxf(s[nt][0], s[nt][1]));
            mx1 = fmaxf(mx1, fmaxf(s[nt][2], s[nt][3]));
        }
        mx0 = fmaxf(mx0, __shfl_xor_sync(0xffffffffu, mx0, 1));
        mx0 = fmaxf(mx0, __shfl_xor_sync(0xffffffffu, mx0, 2));
        mx1 = fmaxf(mx1, __shfl_xor_sync(0xffffffffu, mx1, 1));
        mx1 = fmaxf(mx1, __shfl_xor_sync(0xffffffffu, mx1, 2));
        float mn0 = fmaxf(rm0, mx0), mn1 = fmaxf(rm1, mx1);
        float a0 = rm0 - mn0, a1 = rm1 - mn1;
        float sc0, sc1;
        EX2(sc0, a0);
        EX2(sc1, a1);
        float su0 = 0.f, su1 = 0.f;
#pragma unroll
        for (int nt = 0; nt < 8; nt++) {
            float d0 = s[nt][0] - mn0, d1 = s[nt][1] - mn0;
            float d2 = s[nt][2] - mn1, d3 = s[nt][3] - mn1;
            EX2(s[nt][0], d0);
            EX2(s[nt][1], d1);
            EX2(s[nt][2], d2);
            EX2(s[nt][3], d3);
            su0 += s[nt][0] + s[nt][1];
            su1 += s[nt][2] + s[nt][3];
        }
        su0 += __shfl_xor_sync(0xffffffffu, su0, 1);
        su0 += __shfl_xor_sync(0xffffffffu, su0, 2);
        su1 += __shfl_xor_sync(0xffffffffu, su1, 1);
        su1 += __shfl_xor_sync(0xffffffffu, su1, 2);
        rl0 = rl0 * sc0 + su0;  rm0 = mn0;
        rl1 = rl1 * sc1 + su1;  rm1 = mn1;
#pragma unroll
        for (int nt = 0; nt < 8; nt++) {
            o[nt][0] *= sc0; o[nt][1] *= sc0;
            o[nt][2] *= sc1; o[nt][3] *= sc1;
        }

#pragma unroll
        for (int st = 0; st < 4; st++) {
            uint32_t ph0, ph1, ph2, ph3, pl0, pl1, pl2, pl3;
            CVT_HILO(s[2*st][0],   s[2*st][1],   ph0, pl0);
            CVT_HILO(s[2*st][2],   s[2*st][3],   ph1, pl1);
            CVT_HILO(s[2*st+1][0], s[2*st+1][1], ph2, pl2);
            CVT_HILO(s[2*st+1][2], s[2*st+1][3], ph3, pl3);
#pragma unroll
            for (int p2 = 0; p2 < 4; p2++) {
                uint32_t v0,v1,v2,v3, w0,w1,w2,w3;
                uint32_t va = sVhi + (st*16 + vrow_lane) * RS_F + (p2*2 + vcol) * 16;
                LDM_X4T(v0, v1, v2, v3, va);
                LDM_X4T(w0, w1, w2, w3, va + KVT_B);
                MMA_BF16(o[2*p2][0],o[2*p2][1],o[2*p2][2],o[2*p2][3],
                         ph0,ph1,ph2,ph3, v0,v1);
                MMA_BF16(o[2*p2][0],o[2*p2][1],o[2*p2][2],o[2*p2][3],
                         ph0,ph1,ph2,ph3, w0,w1);
                MMA_BF16(o[2*p2][0],o[2*p2][1],o[2*p2][2],o[2*p2][3],
                         pl0,pl1,pl2,pl3, v0,v1);
                MMA_BF16(o[2*p2+1][0],o[2*p2+1][1],o[2*p2+1][2],o[2*p2+1][3],
                         ph0,ph1,ph2,ph3, v2,v3);
                MMA_BF16(o[2*p2+1][0],o[2*p2+1][1],o[2*p2+1][2],o[2*p2+1][3],
                         ph0,ph1,ph2,ph3, w2,w3);
                MMA_BF16(o[2*p2+1][0],o[2*p2+1][1],o[2*p2+1][2],o[2*p2+1][3],
                         pl0,pl1,pl2,pl3, v2,v3);
            }
        }
    }

    {
        float inv0 = 1.f / rl0, inv1 = 1.f / rl1;
        int t0 = q0 + wid*16 + g, t1 = t0 + 8;
        float* c0p = g_ctx + (long)(b * NT + t0) * NC + h * DHD + t2;
        float* c1p = g_ctx + (long)(b * NT + t1) * NC + h * DHD + t2;
#pragma unroll
        for (int nt = 0; nt < 8; nt++) {
            float2 u0 = {o[nt][0] * inv0, o[nt][1] * inv0};
            float2 u1 = {o[nt][2] * inv1, o[nt][3] * inv1};
            *(float2*)(c0p + nt * 8) = u0;
            *(float2*)(c1p + nt * 8) = u1;
        }
    }
#undef CP_STAGE
#undef BAND_W
}

// ---------------- launch ---------------------------------------------------------
extern "C" void kernel_launch(void* const* d_in, const int* in_sizes, int n_in,
                              void* d_out, int out_size)
{
    const float* x     = (const float*)d_in[0];
    const float* w_qkv = (const float*)d_in[1];
    const float* b_qkv = (const float*)d_in[2];
    const float* w_out = (const float*)d_in[3];
    const float* b_out = (const float*)d_in[4];
    const float* w1    = (const float*)d_in[5];
    const float* b1    = (const float*)d_in[6];
    const float* w2    = (const float*)d_in[7];
    const float* b2    = (const float*)d_in[8];
    float* out = (float*)d_out;

    cudaFuncSetAttribute(flash_kernel, cudaFuncAttributeMaxDynamicSharedMemorySize,
                         FL_SMEM);
    cudaFuncSetAttribute(mm_kernel<0>, cudaFuncAttributeMaxDynamicSharedMemorySize,
                         MM_SMEM_BYTES);
    cudaFuncSetAttribute(mm_kernel<1>, cudaFuncAttributeMaxDynamicSharedMemorySize,
                         MM_SMEM_BYTES);

    rpe_kernel<<<(NDIST + 255) / 256, 256>>>(w1, b1, w2, b2);

    conv_x_kernel<<<NM * NC / 4 / 256, 256>>>(x);

    {   // QKV projection (512 threads / 16 warps, race-fixed pipeline)
        dim3 gq(N3C / BN, NM / BM);
        mm_kernel<0><<<gq, 512, MM_SMEM_BYTES>>>(x, w_qkv, N3C, b_qkv, nullptr);
    }
    {   // flash attention (16 warps)
        dim3 gf(NT / 256, NB * NH);
        flash_kernel<<<gf, 512, FL_SMEM>>>();
    }
    {   // output projection (512 threads / 16 warps)
        dim3 go(NC / BN, NM / BM);
        mm_kernel<1><<<go, 512, MM_SMEM_BYTES>>>(nullptr, w_out, NC, b_out, out);
    }
}

// round 14
// speedup vs baseline: 1.0363x; 1.0363x over previous
#include <cuda_runtime.h>
#include <cuda_bf16.h>
#include <cuda_fp16.h>
#include <math.h>
#include <stdint.h>

#define NB 2
#define NT 2048
#define NC 1024
#define NH 16
#define DHD 64
#define NHID 32
#define N3C 3072
#define NM 4096
#define NDIST 4095
#define MMK 1024
#define BM 128
#define BN 128
#define BKC 32
#define NCHUNK (MMK/BKC)
#define LOG2E 1.4426950408889634f

// ---------------- statics: same 67.2MB footprint as passing R6-R13 ---------------
__device__ __align__(16) __nv_bfloat16 g_qhi[NB*NH*NT*DHD];  // [bh][t][dh], pre-scaled log2e/8
__device__ __align__(16) __nv_bfloat16 g_qlo[NB*NH*NT*DHD];
__device__ __align__(16) __nv_bfloat16 g_khi[NB*NH*NT*DHD];
__device__ __align__(16) __nv_bfloat16 g_klo[NB*NH*NT*DHD];
__device__ __align__(16) __nv_bfloat16 g_vhi[NB*NH*NT*DHD];  // holds fp16 bits
__device__ __align__(16) __nv_bfloat16 g_vlo[NB*NH*NT*DHD];  // holds fp16 bits
// g_ctx doubles as: (a) xhi/xlo bf16 scratch for mm<0>, (b) fp32 attention output.
__device__ __align__(16) float g_ctx[NM*NC];
__device__ float g_bias[NH*NDIST];          // pre-scaled by log2e

// ================= PTX helpers ==================================================
__device__ __forceinline__ uint32_t s2u(const void* p) {
    uint32_t a;
    asm("{ .reg .u64 t; cvta.to.shared.u64 t, %1; cvt.u32.u64 %0, t; }" : "=r"(a) : "l"(p));
    return a;
}
#define CP_ASYNC16(dst, src) \
    asm volatile("cp.async.cg.shared.global [%0], [%1], 16;" :: "r"(dst), "l"(src))
#define CP_COMMIT() asm volatile("cp.async.commit_group;" ::: "memory")
#define CP_WAIT0()  asm volatile("cp.async.wait_group 0;" ::: "memory")

#define LDM_X4(r0,r1,r2,r3,addr) \
    asm volatile("ldmatrix.sync.aligned.m8n8.x4.shared.b16 {%0,%1,%2,%3}, [%4];" \
        : "=r"(r0),"=r"(r1),"=r"(r2),"=r"(r3) : "r"(addr))
#define LDM_X4T(r0,r1,r2,r3,addr) \
    asm volatile("ldmatrix.sync.aligned.m8n8.x4.trans.shared.b16 {%0,%1,%2,%3}, [%4];" \
        : "=r"(r0),"=r"(r1),"=r"(r2),"=r"(r3) : "r"(addr))
#define LDM_X2T(r0,r1,addr) \
    asm volatile("ldmatrix.sync.aligned.m8n8.x2.trans.shared.b16 {%0,%1}, [%2];" \
        : "=r"(r0),"=r"(r1) : "r"(addr))

#define MMA_BF16(c0,c1,c2,c3,a0,a1,a2,a3,b0,b1) \
    asm volatile("mma.sync.aligned.m16n8k16.row.col.f32.bf16.bf16.f32 " \
                 "{%0,%1,%2,%3}, {%4,%5,%6,%7}, {%8,%9}, {%0,%1,%2,%3};" \
                 : "+f"(c0), "+f"(c1), "+f"(c2), "+f"(c3) \
                 : "r"(a0), "r"(a1), "r"(a2), "r"(a3), "r"(b0), "r"(b1))

#define MMA_F16(c0,c1,c2,c3,a0,a1,a2,a3,b0,b1) \
    asm volatile("mma.sync.aligned.m16n8k16.row.col.f32.f16.f16.f32 " \
                 "{%0,%1,%2,%3}, {%4,%5,%6,%7}, {%8,%9}, {%0,%1,%2,%3};" \
                 : "+f"(c0), "+f"(c1), "+f"(c2), "+f"(c3) \
                 : "r"(a0), "r"(a1), "r"(a2), "r"(a3), "r"(b0), "r"(b1))

#define CVT_HILO(x, y, hi, lo) do{ \
    asm("cvt.rn.bf16x2.f32 %0, %1, %2;" : "=r"(hi) : "f"(y), "f"(x)); \
    float _lx = (x) - __uint_as_float((hi) << 16); \
    float _ly = (y) - __uint_as_float((hi) & 0xFFFF0000u); \
    asm("cvt.rn.bf16x2.f32 %0, %1, %2;" : "=r"(lo) : "f"(_ly), "f"(_lx)); \
}while(0)

// fp16 hi/lo split (11-bit mantissa each; hi packs x->lo half, y->hi half)
#define CVT_HILO_F16(x, y, hi, lo) do{ \
    asm("cvt.rn.f16x2.f32 %0, %1, %2;" : "=r"(hi) : "f"(y), "f"(x)); \
    float _fx, _fy; \
    asm("{ .reg .f16 a, b; mov.b32 {a, b}, %2; cvt.f32.f16 %0, a; cvt.f32.f16 %1, b; }" \
        : "=f"(_fx), "=f"(_fy) : "r"(hi)); \
    float _lx = (x) - _fx, _ly = (y) - _fy; \
    asm("cvt.rn.f16x2.f32 %0, %1, %2;" : "=r"(lo) : "f"(_ly), "f"(_lx)); \
}while(0)

#define CVT_F16X2(x, y, d) \
    asm("cvt.rn.f16x2.f32 %0, %1, %2;" : "=r"(d) : "f"(y), "f"(x))

#define EX2(d, s) asm("ex2.approx.ftz.f32 %0, %1;" : "=f"(d) : "f"(s))

// ---------------- RPE bias table (pre-scaled by log2e) --------------------------
__global__ void rpe_kernel(const float* __restrict__ w1, const float* __restrict__ b1,
                           const float* __restrict__ w2, const float* __restrict__ b2)
{
    int d = blockIdx.x * blockDim.x + threadIdx.x;
    if (d >= NDIST) return;
    float rel = (float)(d - (NT - 1));
    float sgn = (rel > 0.f) ? 1.f : ((rel < 0.f) ? -1.f : 0.f);
    float x = sgn * log1pf(fabsf(rel));
    float h[NHID];
#pragma unroll
    for (int j = 0; j < NHID; j++)
        h[j] = fmaxf(fmaf(x, __ldg(&w1[j]), __ldg(&b1[j])), 0.f);
#pragma unroll
    for (int hd = 0; hd < NH; hd++) {
        float acc = __ldg(&b2[hd]);
#pragma unroll
        for (int j = 0; j < NHID; j++)
            acc = fmaf(h[j], __ldg(&w2[j*NH + hd]), acc);
        g_bias[hd*NDIST + d] = acc * LOG2E;
    }
}

// ---------------- x -> bf16 hi/lo (into g_ctx scratch) ---------------------------
__global__ void conv_x_kernel(const float* __restrict__ x) {
    __nv_bfloat16* xhi = (__nv_bfloat16*)g_ctx;
    __nv_bfloat16* xlo = xhi + (long)NM * NC;
    long i = (long)(blockIdx.x * blockDim.x + threadIdx.x) * 4;
    float4 v = *(const float4*)&x[i];
    uint32_t h01, l01, h23, l23;
    CVT_HILO(v.x, v.y, h01, l01);
    CVT_HILO(v.z, v.w, h23, l23);
    *(uint2*)&xhi[i] = make_uint2(h01, h23);
    *(uint2*)&xlo[i] = make_uint2(l01, l23);
}

// ---------------- mma.sync bf16 3-term split GEMM, 256 threads (R11 geometry,
//                  race-fixed pipeline, fp16 V epilogue) --------------------------
#define RS_A 80
#define A_TILE_B (128 * RS_A)
#define RS_B 272
#define B_TILE_B (32 * RS_B)
#define STAGE_B (2*A_TILE_B + 2*B_TILE_B)
#define OFF_AHI 0
#define OFF_ALO A_TILE_B
#define OFF_BHI (2*A_TILE_B)
#define OFF_BLO (2*A_TILE_B + B_TILE_B)
#define MM_SMEM_BYTES (2 * STAGE_B)

template<int MODE>
__global__ void __launch_bounds__(256, 1) mm_kernel(
    const float* __restrict__ Ain, const float* __restrict__ Bin, int ldb,
    const float* __restrict__ bias, float* __restrict__ outp)
{
    extern __shared__ __align__(16) char dsm[];
    const float* __restrict__ Ap = (MODE == 0) ? Ain : g_ctx;
    const __nv_bfloat16* __restrict__ Axhi = (const __nv_bfloat16*)g_ctx;
    const __nv_bfloat16* __restrict__ Axlo = Axhi + (long)NM * NC;

    const int tid = threadIdx.x;
    const int wid = tid >> 5, lane = tid & 31;
    const int bm = blockIdx.y * BM, bn = blockIdx.x * BN;
    const int wm = (wid & 1) * 64, wn = (wid >> 1) * 32;
    const uint32_t sbase = s2u(dsm);

    float acc[4][4][4];
#pragma unroll
    for (int mi = 0; mi < 4; mi++)
#pragma unroll
        for (int ni = 0; ni < 4; ni++)
#pragma unroll
            for (int r = 0; r < 4; r++) acc[mi][ni][r] = 0.f;

    const float* __restrict__ aptr = Ap + (long)(bm + (tid >> 1)) * MMK + (tid & 1) * 16;
    const float* __restrict__ bptr = Bin + (long)(tid >> 3) * ldb + bn + (tid & 7) * 16;
    const int ar = tid >> 1, ah = tid & 1;   // MODE 0 A cp.async geometry

#define CP_A(chunk, stage) do { \
    long off_ = (long)(bm + ar) * MMK + (chunk) * BKC + ah * 16; \
    uint32_t d_ = sbase + (stage) * STAGE_B + ar * RS_A + ah * 32; \
    CP_ASYNC16(d_ + OFF_AHI,      Axhi + off_); \
    CP_ASYNC16(d_ + OFF_AHI + 16, Axhi + off_ + 8); \
    CP_ASYNC16(d_ + OFF_ALO,      Axlo + off_); \
    CP_ASYNC16(d_ + OFF_ALO + 16, Axlo + off_ + 8); \
    CP_COMMIT(); \
} while(0)

    float4 va0, va1, va2, va3, vb0, vb1, vb2, vb3;
#define LOADC(k0) do { \
    if (MODE == 1) { \
        const float* _a = aptr + (k0); \
        va0 = *(const float4*)(_a + 0);  va1 = *(const float4*)(_a + 4); \
        va2 = *(const float4*)(_a + 8);  va3 = *(const float4*)(_a + 12); \
    } \
    const float* _b = bptr + (long)(k0) * ldb; \
    vb0 = *(const float4*)(_b + 0);  vb1 = *(const float4*)(_b + 4); \
    vb2 = *(const float4*)(_b + 8);  vb3 = *(const float4*)(_b + 12); \
} while(0)

    if (MODE == 0) CP_A(0, 0);
    LOADC(0);

    const int laneA_row = lane & 15, laneA_half = (lane >> 4) * 16;
    const uint32_t laneB_row = (lane & 7) + ((lane >> 3) & 1) * 8;

    for (int i = 0; i < NCHUNK; i++) {
        const int buf = i & 1;
        char* sp = dsm + buf * STAGE_B;
        if (MODE == 1) {
            char* pa = sp + (tid >> 1) * RS_A + (tid & 1) * 32;
            uint32_t h0,h1,h2,h3,h4,h5,h6,h7, l0,l1,l2,l3,l4,l5,l6,l7;
            CVT_HILO(va0.x, va0.y, h0, l0);  CVT_HILO(va0.z, va0.w, h1, l1);
            CVT_HILO(va1.x, va1.y, h2, l2);  CVT_HILO(va1.z, va1.w, h3, l3);
            CVT_HILO(va2.x, va2.y, h4, l4);  CVT_HILO(va2.z, va2.w, h5, l5);
            CVT_HILO(va3.x, va3.y, h6, l6);  CVT_HILO(va3.z, va3.w, h7, l7);
            *(uint4*)(pa + OFF_AHI +  0) = make_uint4(h0, h1, h2, h3);
            *(uint4*)(pa + OFF_AHI + 16) = make_uint4(h4, h5, h6, h7);
            *(uint4*)(pa + OFF_ALO +  0) = make_uint4(l0, l1, l2, l3);
            *(uint4*)(pa + OFF_ALO + 16) = make_uint4(l4, l5, l6, l7);
        }
        {
            char* pb = sp + (tid >> 3) * RS_B + (tid & 7) * 32;
            uint32_t h0,h1,h2,h3,h4,h5,h6,h7, l0,l1,l2,l3,l4,l5,l6,l7;
            CVT_HILO(vb0.x, vb0.y, h0, l0);  CVT_HILO(vb0.z, vb0.w, h1, l1);
            CVT_HILO(vb1.x, vb1.y, h2, l2);  CVT_HILO(vb1.z, vb1.w, h3, l3);
            CVT_HILO(vb2.x, vb2.y, h4, l4);  CVT_HILO(vb2.z, vb2.w, h5, l5);
            CVT_HILO(vb3.x, vb3.y, h6, l6);  CVT_HILO(vb3.z, vb3.w, h7, l7);
            *(uint4*)(pb + OFF_BHI +  0) = make_uint4(h0, h1, h2, h3);
            *(uint4*)(pb + OFF_BHI + 16) = make_uint4(h4, h5, h6, h7);
            *(uint4*)(pb + OFF_BLO +  0) = make_uint4(l0, l1, l2, l3);
            *(uint4*)(pb + OFF_BLO + 16) = make_uint4(l4, l5, l6, l7);
        }
        // wait for this stage's A dma before the barrier (cross-thread visibility)
        if (MODE == 0) CP_WAIT0();
        __syncthreads();
        // all threads finished MMA(i-1) (last reader of stage buf^1): safe to refill
        if (MODE == 0 && i + 1 < NCHUNK) CP_A(i + 1, buf ^ 1);
        if (i + 1 < NCHUNK) LOADC((i + 1) * BKC);

        const uint32_t stb  = sbase + buf * STAGE_B;
        const uint32_t sAhi = stb + OFF_AHI;
        const uint32_t sAlo = stb + OFF_ALO;
        const uint32_t sBhi = stb + OFF_BHI;
        const uint32_t sBlo = stb + OFF_BLO;

#pragma unroll
        for (int kk = 0; kk < 2; kk++) {
            const uint32_t koffA = kk * 32;
            const uint32_t browB = (kk * 16 + laneB_row) * RS_B;
            uint32_t bh0,bh1,bh2,bh3,bh4,bh5,bh6,bh7;
            uint32_t bl0,bl1,bl2,bl3,bl4,bl5,bl6,bl7;
            LDM_X2T(bh0, bh1, sBhi + browB + (wn + 0*8) * 2);
            LDM_X2T(bh2, bh3, sBhi + browB + (wn + 1*8) * 2);
            LDM_X2T(bh4, bh5, sBhi + browB + (wn + 2*8) * 2);
            LDM_X2T(bh6, bh7, sBhi + browB + (wn + 3*8) * 2);
            LDM_X2T(bl0, bl1, sBlo + browB + (wn + 0*8) * 2);
            LDM_X2T(bl2, bl3, sBlo + browB + (wn + 1*8) * 2);
            LDM_X2T(bl4, bl5, sBlo + browB + (wn + 2*8) * 2);
            LDM_X2T(bl6, bl7, sBlo + browB + (wn + 3*8) * 2);
#pragma unroll
            for (int mi = 0; mi < 4; mi++) {
                uint32_t a0, a1, a2, a3;
                uint32_t aa = sAhi + (wm + mi*16 + laneA_row) * RS_A + laneA_half + koffA;
                LDM_X4(a0, a1, a2, a3, aa);
                MMA_BF16(acc[mi][0][0],acc[mi][0][1],acc[mi][0][2],acc[mi][0][3], a0,a1,a2,a3, bh0,bh1);
                MMA_BF16(acc[mi][1][0],acc[mi][1][1],acc[mi][1][2],acc[mi][1][3], a0,a1,a2,a3, bh2,bh3);
                MMA_BF16(acc[mi][2][0],acc[mi][2][1],acc[mi][2][2],acc[mi][2][3], a0,a1,a2,a3, bh4,bh5);
                MMA_BF16(acc[mi][3][0],acc[mi][3][1],acc[mi][3][2],acc[mi][3][3], a0,a1,a2,a3, bh6,bh7);
                MMA_BF16(acc[mi][0][0],acc[mi][0][1],acc[mi][0][2],acc[mi][0][3], a0,a1,a2,a3, bl0,bl1);
                MMA_BF16(acc[mi][1][0],acc[mi][1][1],acc[mi][1][2],acc[mi][1][3], a0,a1,a2,a3, bl2,bl3);
                MMA_BF16(acc[mi][2][0],acc[mi][2][1],acc[mi][2][2],acc[mi][2][3], a0,a1,a2,a3, bl4,bl5);
                MMA_BF16(acc[mi][3][0],acc[mi][3][1],acc[mi][3][2],acc[mi][3][3], a0,a1,a2,a3, bl6,bl7);
            }
#pragma unroll
            for (int mi = 0; mi < 4; mi++) {
                uint32_t a0, a1, a2, a3;
                uint32_t aa = sAlo + (wm + mi*16 + laneA_row) * RS_A + laneA_half + koffA;
                LDM_X4(a0, a1, a2, a3, aa);
                MMA_BF16(acc[mi][0][0],acc[mi][0][1],acc[mi][0][2],acc[mi][0][3], a0,a1,a2,a3, bh0,bh1);
                MMA_BF16(acc[mi][1][0],acc[mi][1][1],acc[mi][1][2],acc[mi][1][3], a0,a1,a2,a3, bh2,bh3);
                MMA_BF16(acc[mi][2][0],acc[mi][2][1],acc[mi][2][2],acc[mi][2][3], a0,a1,a2,a3, bh4,bh5);
                MMA_BF16(acc[mi][3][0],acc[mi][3][1],acc[mi][3][2],acc[mi][3][3], a0,a1,a2,a3, bh6,bh7);
            }
        }
    }
#undef LOADC
#undef CP_A

    const int lane4 = lane >> 2, lane2 = (lane & 3) * 2;
#pragma unroll
    for (int mi = 0; mi < 4; mi++) {
        int r0 = bm + wm + mi*16 + lane4;
        int r1 = r0 + 8;
#pragma unroll
        for (int ni = 0; ni < 4; ni++) {
            int ng = bn + wn + ni*8 + lane2;
            float bz0 = bias[ng], bz1 = bias[ng + 1];
            float c0 = acc[mi][ni][0] + bz0, c1 = acc[mi][ni][1] + bz1;
            float c2 = acc[mi][ni][2] + bz0, c3 = acc[mi][ni][3] + bz1;
            if (MODE == 1) {
                float2 v0 = {c0, c1}, v1 = {c2, c3};
                *(float2*)&outp[(long)r0 * NC + ng] = v0;
                *(float2*)&outp[(long)r1 * NC + ng] = v1;
            } else {
                const int sel = bn >> 10;
                int n = ng & (NC - 1);
                int head = n >> 6, dh = n & (DHD - 1);
                int b0 = r0 >> 11, t0 = r0 & (NT - 1);
                int b1 = r1 >> 11, t1 = r1 & (NT - 1);
                uint32_t hi0, lo0, hi1, lo1;
                if (sel == 0) {
                    const float qs = 0.125f * LOG2E;
                    c0 *= qs; c1 *= qs; c2 *= qs; c3 *= qs;
                }
                if (sel == 2) {   // V stored as fp16 hi/lo (PV runs on fp16 MMA)
                    CVT_HILO_F16(c0, c1, hi0, lo0);
                    CVT_HILO_F16(c2, c3, hi1, lo1);
                } else {
                    CVT_HILO(c0, c1, hi0, lo0);
                    CVT_HILO(c2, c3, hi1, lo1);
                }
                __nv_bfloat16* dhi = (sel == 0) ? g_qhi : (sel == 1) ? g_khi : g_vhi;
                __nv_bfloat16* dlo = (sel == 0) ? g_qlo : (sel == 1) ? g_klo : g_vlo;
                long e0 = ((long)(((b0 << 4) + head) * NT + t0)) * DHD + dh;
                long e1 = ((long)(((b1 << 4) + head) * NT + t1)) * DHD + dh;
                *(uint32_t*)(dhi + e0) = hi0;  *(uint32_t*)(dlo + e0) = lo0;
                *(uint32_t*)(dhi + e1) = hi1;  *(uint32_t*)(dlo + e1) = lo1;
            }
        }
    }
}

// ---------------- tensor-core flash attention, BQ=256, 16 warps, fp16 PV --------
#define RS_F 144
#define QTILE_B (256 * RS_F)
#define KVT_B   (64 * RS_F)
#define STAGE_F (4 * KVT_B)
#define OFF_Q    0
#define OFF_ST   (2 * QTILE_B)
#define OFF_BAND (OFF_ST + 2 * STAGE_F)
#define FL_SMEM  (OFF_BAND + 2 * 336 * 8)

__global__ void __launch_bounds__(512, 1) flash_kernel()
{
    extern __shared__ __align__(16) char fsm[];
    const int tid = threadIdx.x, wid = tid >> 5, lane = tid & 31;
    const int bh = blockIdx.y, h = bh & (NH - 1), b = bh >> 4;
    const int q0 = blockIdx.x * 256;
    const uint32_t sb = s2u(fsm);
    const long kvbase = (long)bh * NT * DHD;
    const int hb = h * NDIST;
    float2* bandp = (float2*)(fsm + OFF_BAND);

    {
        int a = tid >> 8, row = tid & 255;
        const uint4* src = (const uint4*)((a ? g_qlo : g_qhi) + kvbase + (long)(q0 + row) * DHD);
        uint4* dst = (uint4*)(fsm + OFF_Q + a * QTILE_B + row * RS_F);
#pragma unroll
        for (int u = 0; u < 8; u++) dst[u] = src[u];
    }

#define CP_STAGE(tile, buf) do { \
    int a_ = tid >> 7; int r2_ = tid & 127; int row_ = r2_ >> 1; \
    const __nv_bfloat16* g_ = (a_ == 0) ? g_khi : (a_ == 1) ? g_klo : (a_ == 2) ? g_vhi : g_vlo; \
    const char* src_ = (const char*)(g_ + kvbase + (long)((tile) * 64 + row_) * DHD) + (r2_ & 1) * 64; \
    uint32_t dst_ = sb + OFF_ST + (buf) * STAGE_F + a_ * KVT_B + row_ * RS_F + (r2_ & 1) * 64; \
    CP_ASYNC16(dst_ +  0, src_ +  0); CP_ASYNC16(dst_ + 16, src_ + 16); \
    CP_ASYNC16(dst_ + 32, src_ + 32); CP_ASYNC16(dst_ + 48, src_ + 48); \
} while(0)

#define BAND_W(tile, buf) do { \
    int base_ = q0 - (tile) * 64 + 1984; \
    if (tid < 319) { \
        int d0_ = base_ + tid; int d1_ = d0_ - 1; if (d1_ < 0) d1_ = 0; \
        bandp[(buf) * 336 + tid] = make_float2(g_bias[hb + d0_], g_bias[hb + d1_]); \
    } \
} while(0)

    CP_STAGE(0, 0);
    CP_COMMIT();
    BAND_W(0, 0);

    float o[8][4];
#pragma unroll
    for (int nt = 0; nt < 8; nt++)
#pragma unroll
        for (int r = 0; r < 4; r++) o[nt][r] = 0.f;
    float rm0 = -1e30f, rm1 = -1e30f, rl0 = 0.f, rl1 = 0.f;

    const int g = lane >> 2, t2 = (lane & 3) * 2;
    const int krow_lane = ((lane >> 4) & 1) * 8 + (lane & 7);
    const int kbyte     = ((lane >> 3) & 1) * 16;
    const int vrow_lane = ((lane >> 3) & 1) * 8 + (lane & 7);
    const int vcol      = (lane >> 4);
    const int qrow_lane = lane & 15;
    const int qbyte     = (lane >> 4) * 16;
    const int e0 = wid * 16 + g + 63 - t2;

    for (int i = 0; i < 32; i++) {
        const int buf = i & 1;
        CP_WAIT0();
        __syncthreads();
        if (i + 1 < 32) {
            CP_STAGE(i + 1, buf ^ 1);
            CP_COMMIT();
            BAND_W(i + 1, buf ^ 1);
        }

        const uint32_t stg  = sb + OFF_ST + buf * STAGE_F;
        const uint32_t sKhi = stg;
        const uint32_t sVhi = stg + 2 * KVT_B;

        float s[8][4];
#pragma unroll
        for (int nt = 0; nt < 8; nt++)
#pragma unroll
            for (int r = 0; r < 4; r++) s[nt][r] = 0.f;

#pragma unroll
        for (int kt = 0; kt < 4; kt++) {
            uint32_t qh0, qh1, qh2, qh3, ql0, ql1, ql2, ql3;
            uint32_t qa = sb + OFF_Q + (wid*16 + qrow_lane) * RS_F + qbyte + kt * 32;
            LDM_X4(qh0, qh1, qh2, qh3, qa);
            LDM_X4(ql0, ql1, ql2, ql3, qa + QTILE_B);
#pragma unroll
            for (int p = 0; p < 4; p++) {
                uint32_t k0,k1,k2,k3, n0,n1,n2,n3;
                uint32_t ka = sKhi + (p*16 + krow_lane) * RS_F + kbyte + kt * 32;
                LDM_X4(k0, k1, k2, k3, ka);
                LDM_X4(n0, n1, n2, n3, ka + KVT_B);
                MMA_BF16(s[2*p][0],s[2*p][1],s[2*p][2],s[2*p][3],
                         qh0,qh1,qh2,qh3, k0,k1);
                MMA_BF16(s[2*p][0],s[2*p][1],s[2*p][2],s[2*p][3],
                         qh0,qh1,qh2,qh3, n0,n1);
                MMA_BF16(s[2*p][0],s[2*p][1],s[2*p][2],s[2*p][3],
                         ql0,ql1,ql2,ql3, k0,k1);
                MMA_BF16(s[2*p+1][0],s[2*p+1][1],s[2*p+1][2],s[2*p+1][3],
                         qh0,qh1,qh2,qh3, k2,k3);
                MMA_BF16(s[2*p+1][0],s[2*p+1][1],s[2*p+1][2],s[2*p+1][3],
                         qh0,qh1,qh2,qh3, n2,n3);
                MMA_BF16(s[2*p+1][0],s[2*p+1][1],s[2*p+1][2],s[2*p+1][3],
                         ql0,ql1,ql2,ql3, k2,k3);
            }
        }

        const float2* bd = bandp + buf * 336;
        float mx0 = -1e30f, mx1 = -1e30f;
#pragma unroll
        for (int nt = 0; nt < 8; nt++) {
            float2 b0v = bd[e0 - 8*nt];
            float2 b1v = bd[e0 + 8 - 8*nt];
            s[nt][0] += b0v.x;  s[nt][1] += b0v.y;
            s[nt][2] += b1v.x;  s[nt][3] += b1v.y;
            mx0 = fmaxf(mx0, fmaxf(s[nt][0], s[nt][1]));
            mx1 = fmaxf(mx1, fmaxf(s[nt][2], s[nt][3]));
        }
        mx0 = fmaxf(mx0, __shfl_xor_sync(0xffffffffu, mx0, 1));
        mx0 = fmaxf(mx0, __shfl_xor_sync(0xffffffffu, mx0, 2));
        mx1 = fmaxf(mx1, __shfl_xor_sync(0xffffffffu, mx1, 1));
        mx1 = fmaxf(mx1, __shfl_xor_sync(0xffffffffu, mx1, 2));
        float mn0 = fmaxf(rm0, mx0), mn1 = fmaxf(rm1, mx1);
        float a0 = rm0 - mn0, a1 = rm1 - mn1;
        float sc0, sc1;
        EX2(sc0, a0);
        EX2(sc1, a1);
        float su0 = 0.f, su1 = 0.f;
#pragma unroll
        for (int nt = 0; nt < 8; nt++) {
            float d0 = s[nt][0] - mn0, d1 = s[nt][1] - mn0;
            float d2 = s[nt][2] - mn1, d3 = s[nt][3] - mn1;
            EX2(s[nt][0], d0);
            EX2(s[nt][1], d1);
            EX2(s[nt][2], d2);
            EX2(s[nt][3], d3);
            su0 += s[nt][0] + s[nt][1];
            su1 += s[nt][2] + s[nt][3];
        }
        su0 += __shfl_xor_sync(0xffffffffu, su0, 1);
        su0 += __shfl_xor_sync(0xffffffffu, su0, 2);
        su1 += __shfl_xor_sync(0xffffffffu, su1, 1);
        su1 += __shfl_xor_sync(0xffffffffu, su1, 2);
        rl0 = rl0 * sc0 + su0;  rm0 = mn0;
        rl1 = rl1 * sc1 + su1;  rm1 = mn1;
#pragma unroll
        for (int nt = 0; nt < 8; nt++) {
            o[nt][0] *= sc0; o[nt][1] *= sc0;
            o[nt][2] *= sc1; o[nt][3] *= sc1;
        }

        // ---- O += P V : P single fp16 term, V fp16 hi/lo (2 MMA per group) ----
#pragma unroll
        for (int st = 0; st < 4; st++) {
            uint32_t p0, p1, p2r, p3;
            CVT_F16X2(s[2*st][0],   s[2*st][1],   p0);
            CVT_F16X2(s[2*st][2],   s[2*st][3],   p1);
            CVT_F16X2(s[2*st+1][0], s[2*st+1][1], p2r);
            CVT_F16X2(s[2*st+1][2], s[2*st+1][3], p3);
#pragma unroll
            for (int p2 = 0; p2 < 4; p2++) {
                uint32_t v0,v1,v2,v3, w0,w1,w2,w3;
                uint32_t va = sVhi + (st*16 + vrow_lane) * RS_F + (p2*2 + vcol) * 16;
                LDM_X4T(v0, v1, v2, v3, va);
                LDM_X4T(w0, w1, w2, w3, va + KVT_B);
                MMA_F16(o[2*p2][0],o[2*p2][1],o[2*p2][2],o[2*p2][3],
                        p0,p1,p2r,p3, v0,v1);
                MMA_F16(o[2*p2][0],o[2*p2][1],o[2*p2][2],o[2*p2][3],
                        p0,p1,p2r,p3, w0,w1);
                MMA_F16(o[2*p2+1][0],o[2*p2+1][1],o[2*p2+1][2],o[2*p2+1][3],
                        p0,p1,p2r,p3, v2,v3);
                MMA_F16(o[2*p2+1][0],o[2*p2+1][1],o[2*p2+1][2],o[2*p2+1][3],
                        p0,p1,p2r,p3, w2,w3);
            }
        }
    }

    {
        float inv0 = 1.f / rl0, inv1 = 1.f / rl1;
        int t0 = q0 + wid*16 + g, t1 = t0 + 8;
        float* c0p = g_ctx + (long)(b * NT + t0) * NC + h * DHD + t2;
        float* c1p = g_ctx + (long)(b * NT + t1) * NC + h * DHD + t2;
#pragma unroll
        for (int nt = 0; nt < 8; nt++) {
            float2 u0 = {o[nt][0] * inv0, o[nt][1] * inv0};
            float2 u1 = {o[nt][2] * inv1, o[nt][3] * inv1};
            *(float2*)(c0p + nt * 8) = u0;
            *(float2*)(c1p + nt * 8) = u1;
        }
    }
#undef CP_STAGE
#undef BAND_W
}

// ---------------- launch ---------------------------------------------------------
extern "C" void kernel_launch(void* const* d_in, const int* in_sizes, int n_in,
                              void* d_out, int out_size)
{
    const float* x     = (const float*)d_in[0];
    const float* w_qkv = (const float*)d_in[1];
    const float* b_qkv = (const float*)d_in[2];
    const float* w_out = (const float*)d_in[3];
    const float* b_out = (const float*)d_in[4];
    const float* w1    = (const float*)d_in[5];
    const float* b1    = (const float*)d_in[6];
    const float* w2    = (const float*)d_in[7];
    const float* b2    = (const float*)d_in[8];
    float* out = (float*)d_out;

    cudaFuncSetAttribute(flash_kernel, cudaFuncAttributeMaxDynamicSharedMemorySize,
                         FL_SMEM);
    cudaFuncSetAttribute(mm_kernel<0>, cudaFuncAttributeMaxDynamicSharedMemorySize,
                         MM_SMEM_BYTES);
    cudaFuncSetAttribute(mm_kernel<1>, cudaFuncAttributeMaxDynamicSharedMemorySize,
                         MM_SMEM_BYTES);

    rpe_kernel<<<(NDIST + 255) / 256, 256>>>(w1, b1, w2, b2);

    conv_x_kernel<<<NM * NC / 4 / 256, 256>>>(x);

    {   // QKV projection (256 threads, race-fixed pipeline, fp16 V epilogue)
        dim3 gq(N3C / BN, NM / BM);
        mm_kernel<0><<<gq, 256, MM_SMEM_BYTES>>>(x, w_qkv, N3C, b_qkv, nullptr);
    }
    {   // flash attention (16 warps, fp16 PV)
        dim3 gf(NT / 256, NB * NH);
        flash_kernel<<<gf, 512, FL_SMEM>>>();
    }
    {   // output projection (256 threads)
        dim3 go(NC / BN, NM / BM);
        mm_kernel<1><<<go, 256, MM_SMEM_BYTES>>>(nullptr, w_out, NC, b_out, out);
    }
}

// round 15
// speedup vs baseline: 1.1131x; 1.0741x over previous
#include <cuda_runtime.h>
#include <cuda_bf16.h>
#include <cuda_fp16.h>
#include <math.h>
#include <stdint.h>

#define NB 2
#define NT 2048
#define NC 1024
#define NH 16
#define DHD 64
#define NHID 32
#define N3C 3072
#define NM 4096
#define NDIST 4095
#define MMK 1024
#define BM 128
#define BN 128
#define BKC 32
#define NCHUNK (MMK/BKC)
#define LOG2E 1.4426950408889634f

// ---------------- statics: same 67.2MB footprint as passing R6-R14 ---------------
__device__ __align__(16) __nv_bfloat16 g_qhi[NB*NH*NT*DHD];  // bf16, pre-scaled log2e/8
__device__ __align__(16) __nv_bfloat16 g_qlo[NB*NH*NT*DHD];
__device__ __align__(16) __nv_bfloat16 g_khi[NB*NH*NT*DHD];
__device__ __align__(16) __nv_bfloat16 g_klo[NB*NH*NT*DHD];
__device__ __align__(16) __nv_bfloat16 g_vhi[NB*NH*NT*DHD];  // fp16 (single-term V)
__device__ __align__(16) __nv_bfloat16 g_vlo[NB*NH*NT*DHD];  // unused (kept for footprint)
// g_ctx region: (a) x bf16 hi/lo scratch for mm<0>; (b) ctx bf16 hi/lo (flash -> mm<1>)
__device__ __align__(16) float g_ctx[NM*NC];
__device__ float g_bias[NH*NDIST];          // pre-scaled by log2e

// ================= PTX helpers ==================================================
__device__ __forceinline__ uint32_t s2u(const void* p) {
    uint32_t a;
    asm("{ .reg .u64 t; cvta.to.shared.u64 t, %1; cvt.u32.u64 %0, t; }" : "=r"(a) : "l"(p));
    return a;
}
#define CP_ASYNC16(dst, src) \
    asm volatile("cp.async.cg.shared.global [%0], [%1], 16;" :: "r"(dst), "l"(src))
#define CP_COMMIT() asm volatile("cp.async.commit_group;" ::: "memory")
#define CP_WAIT0()  asm volatile("cp.async.wait_group 0;" ::: "memory")

#define LDM_X4(r0,r1,r2,r3,addr) \
    asm volatile("ldmatrix.sync.aligned.m8n8.x4.shared.b16 {%0,%1,%2,%3}, [%4];" \
        : "=r"(r0),"=r"(r1),"=r"(r2),"=r"(r3) : "r"(addr))
#define LDM_X4T(r0,r1,r2,r3,addr) \
    asm volatile("ldmatrix.sync.aligned.m8n8.x4.trans.shared.b16 {%0,%1,%2,%3}, [%4];" \
        : "=r"(r0),"=r"(r1),"=r"(r2),"=r"(r3) : "r"(addr))
#define LDM_X2T(r0,r1,addr) \
    asm volatile("ldmatrix.sync.aligned.m8n8.x2.trans.shared.b16 {%0,%1}, [%2];" \
        : "=r"(r0),"=r"(r1) : "r"(addr))

#define MMA_BF16(c0,c1,c2,c3,a0,a1,a2,a3,b0,b1) \
    asm volatile("mma.sync.aligned.m16n8k16.row.col.f32.bf16.bf16.f32 " \
                 "{%0,%1,%2,%3}, {%4,%5,%6,%7}, {%8,%9}, {%0,%1,%2,%3};" \
                 : "+f"(c0), "+f"(c1), "+f"(c2), "+f"(c3) \
                 : "r"(a0), "r"(a1), "r"(a2), "r"(a3), "r"(b0), "r"(b1))

#define MMA_F16(c0,c1,c2,c3,a0,a1,a2,a3,b0,b1) \
    asm volatile("mma.sync.aligned.m16n8k16.row.col.f32.f16.f16.f32 " \
                 "{%0,%1,%2,%3}, {%4,%5,%6,%7}, {%8,%9}, {%0,%1,%2,%3};" \
                 : "+f"(c0), "+f"(c1), "+f"(c2), "+f"(c3) \
                 : "r"(a0), "r"(a1), "r"(a2), "r"(a3), "r"(b0), "r"(b1))

#define CVT_HILO(x, y, hi, lo) do{ \
    asm("cvt.rn.bf16x2.f32 %0, %1, %2;" : "=r"(hi) : "f"(y), "f"(x)); \
    float _lx = (x) - __uint_as_float((hi) << 16); \
    float _ly = (y) - __uint_as_float((hi) & 0xFFFF0000u); \
    asm("cvt.rn.bf16x2.f32 %0, %1, %2;" : "=r"(lo) : "f"(_ly), "f"(_lx)); \
}while(0)

#define CVT_F16X2(x, y, d) \
    asm("cvt.rn.f16x2.f32 %0, %1, %2;" : "=r"(d) : "f"(y), "f"(x))

#define EX2(d, s) asm("ex2.approx.ftz.f32 %0, %1;" : "=f"(d) : "f"(s))

// ---------------- RPE bias table (pre-scaled by log2e) --------------------------
__global__ void rpe_kernel(const float* __restrict__ w1, const float* __restrict__ b1,
                           const float* __restrict__ w2, const float* __restrict__ b2)
{
    int d = blockIdx.x * blockDim.x + threadIdx.x;
    if (d >= NDIST) return;
    float rel = (float)(d - (NT - 1));
    float sgn = (rel > 0.f) ? 1.f : ((rel < 0.f) ? -1.f : 0.f);
    float x = sgn * log1pf(fabsf(rel));
    float h[NHID];
#pragma unroll
    for (int j = 0; j < NHID; j++)
        h[j] = fmaxf(fmaf(x, __ldg(&w1[j]), __ldg(&b1[j])), 0.f);
#pragma unroll
    for (int hd = 0; hd < NH; hd++) {
        float acc = __ldg(&b2[hd]);
#pragma unroll
        for (int j = 0; j < NHID; j++)
            acc = fmaf(h[j], __ldg(&w2[j*NH + hd]), acc);
        g_bias[hd*NDIST + d] = acc * LOG2E;
    }
}

// ---------------- x -> bf16 hi/lo (into g_ctx scratch) ---------------------------
__global__ void conv_x_kernel(const float* __restrict__ x) {
    __nv_bfloat16* xhi = (__nv_bfloat16*)g_ctx;
    __nv_bfloat16* xlo = xhi + (long)NM * NC;
    long i = (long)(blockIdx.x * blockDim.x + threadIdx.x) * 4;
    float4 v = *(const float4*)&x[i];
    uint32_t h01, l01, h23, l23;
    CVT_HILO(v.x, v.y, h01, l01);
    CVT_HILO(v.z, v.w, h23, l23);
    *(uint2*)&xhi[i] = make_uint2(h01, h23);
    *(uint2*)&xlo[i] = make_uint2(l01, l23);
}

// ---------------- mma.sync bf16 3-term split GEMM, 256 threads -------------------
// A always pre-converted bf16 hi/lo in the g_ctx region (x for MODE 0, ctx for
// MODE 1), streamed via race-fixed cp.async. B fp32, converted in-kernel.
#define RS_A 80
#define A_TILE_B (128 * RS_A)
#define RS_B 272
#define B_TILE_B (32 * RS_B)
#define STAGE_B (2*A_TILE_B + 2*B_TILE_B)
#define OFF_AHI 0
#define OFF_ALO A_TILE_B
#define OFF_BHI (2*A_TILE_B)
#define OFF_BLO (2*A_TILE_B + B_TILE_B)
#define MM_SMEM_BYTES (2 * STAGE_B)

template<int MODE>
__global__ void __launch_bounds__(256, 1) mm_kernel(
    const float* __restrict__ Bin, int ldb,
    const float* __restrict__ bias, float* __restrict__ outp)
{
    extern __shared__ __align__(16) char dsm[];
    const __nv_bfloat16* __restrict__ Axhi = (const __nv_bfloat16*)g_ctx;
    const __nv_bfloat16* __restrict__ Axlo = Axhi + (long)NM * NC;

    const int tid = threadIdx.x;
    const int wid = tid >> 5, lane = tid & 31;
    const int bm = blockIdx.y * BM, bn = blockIdx.x * BN;
    const int wm = (wid & 1) * 64, wn = (wid >> 1) * 32;
    const uint32_t sbase = s2u(dsm);

    float acc[4][4][4];
#pragma unroll
    for (int mi = 0; mi < 4; mi++)
#pragma unroll
        for (int ni = 0; ni < 4; ni++)
#pragma unroll
            for (int r = 0; r < 4; r++) acc[mi][ni][r] = 0.f;

    const float* __restrict__ bptr = Bin + (long)(tid >> 3) * ldb + bn + (tid & 7) * 16;
    const int ar = tid >> 1, ah = tid & 1;

#define CP_A(chunk, stage) do { \
    long off_ = (long)(bm + ar) * MMK + (chunk) * BKC + ah * 16; \
    uint32_t d_ = sbase + (stage) * STAGE_B + ar * RS_A + ah * 32; \
    CP_ASYNC16(d_ + OFF_AHI,      Axhi + off_); \
    CP_ASYNC16(d_ + OFF_AHI + 16, Axhi + off_ + 8); \
    CP_ASYNC16(d_ + OFF_ALO,      Axlo + off_); \
    CP_ASYNC16(d_ + OFF_ALO + 16, Axlo + off_ + 8); \
    CP_COMMIT(); \
} while(0)

    float4 vb0, vb1, vb2, vb3;
#define LOADC(k0) do { \
    const float* _b = bptr + (long)(k0) * ldb; \
    vb0 = *(const float4*)(_b + 0);  vb1 = *(const float4*)(_b + 4); \
    vb2 = *(const float4*)(_b + 8);  vb3 = *(const float4*)(_b + 12); \
} while(0)

    CP_A(0, 0);
    LOADC(0);

    const int laneA_row = lane & 15, laneA_half = (lane >> 4) * 16;
    const uint32_t laneB_row = (lane & 7) + ((lane >> 3) & 1) * 8;

    for (int i = 0; i < NCHUNK; i++) {
        const int buf = i & 1;
        char* sp = dsm + buf * STAGE_B;
        {
            char* pb = sp + (tid >> 3) * RS_B + (tid & 7) * 32;
            uint32_t h0,h1,h2,h3,h4,h5,h6,h7, l0,l1,l2,l3,l4,l5,l6,l7;
            CVT_HILO(vb0.x, vb0.y, h0, l0);  CVT_HILO(vb0.z, vb0.w, h1, l1);
            CVT_HILO(vb1.x, vb1.y, h2, l2);  CVT_HILO(vb1.z, vb1.w, h3, l3);
            CVT_HILO(vb2.x, vb2.y, h4, l4);  CVT_HILO(vb2.z, vb2.w, h5, l5);
            CVT_HILO(vb3.x, vb3.y, h6, l6);  CVT_HILO(vb3.z, vb3.w, h7, l7);
            *(uint4*)(pb + OFF_BHI +  0) = make_uint4(h0, h1, h2, h3);
            *(uint4*)(pb + OFF_BHI + 16) = make_uint4(h4, h5, h6, h7);
            *(uint4*)(pb + OFF_BLO +  0) = make_uint4(l0, l1, l2, l3);
            *(uint4*)(pb + OFF_BLO + 16) = make_uint4(l4, l5, l6, l7);
        }
        CP_WAIT0();
        __syncthreads();
        // all threads finished MMA(i-1) (last reader of stage buf^1): safe to refill
        if (i + 1 < NCHUNK) { CP_A(i + 1, buf ^ 1); LOADC((i + 1) * BKC); }

        const uint32_t stb  = sbase + buf * STAGE_B;
        const uint32_t sAhi = stb + OFF_AHI;
        const uint32_t sAlo = stb + OFF_ALO;
        const uint32_t sBhi = stb + OFF_BHI;
        const uint32_t sBlo = stb + OFF_BLO;

#pragma unroll
        for (int kk = 0; kk < 2; kk++) {
            const uint32_t koffA = kk * 32;
            const uint32_t browB = (kk * 16 + laneB_row) * RS_B;
            uint32_t bh0,bh1,bh2,bh3,bh4,bh5,bh6,bh7;
            uint32_t bl0,bl1,bl2,bl3,bl4,bl5,bl6,bl7;
            LDM_X2T(bh0, bh1, sBhi + browB + (wn + 0*8) * 2);
            LDM_X2T(bh2, bh3, sBhi + browB + (wn + 1*8) * 2);
            LDM_X2T(bh4, bh5, sBhi + browB + (wn + 2*8) * 2);
            LDM_X2T(bh6, bh7, sBhi + browB + (wn + 3*8) * 2);
            LDM_X2T(bl0, bl1, sBlo + browB + (wn + 0*8) * 2);
            LDM_X2T(bl2, bl3, sBlo + browB + (wn + 1*8) * 2);
            LDM_X2T(bl4, bl5, sBlo + browB + (wn + 2*8) * 2);
            LDM_X2T(bl6, bl7, sBlo + browB + (wn + 3*8) * 2);
#pragma unroll
            for (int mi = 0; mi < 4; mi++) {
                uint32_t a0, a1, a2, a3;
                uint32_t aa = sAhi + (wm + mi*16 + laneA_row) * RS_A + laneA_half + koffA;
                LDM_X4(a0, a1, a2, a3, aa);
                MMA_BF16(acc[mi][0][0],acc[mi][0][1],acc[mi][0][2],acc[mi][0][3], a0,a1,a2,a3, bh0,bh1);
                MMA_BF16(acc[mi][1][0],acc[mi][1][1],acc[mi][1][2],acc[mi][1][3], a0,a1,a2,a3, bh2,bh3);
                MMA_BF16(acc[mi][2][0],acc[mi][2][1],acc[mi][2][2],acc[mi][2][3], a0,a1,a2,a3, bh4,bh5);
                MMA_BF16(acc[mi][3][0],acc[mi][3][1],acc[mi][3][2],acc[mi][3][3], a0,a1,a2,a3, bh6,bh7);
                MMA_BF16(acc[mi][0][0],acc[mi][0][1],acc[mi][0][2],acc[mi][0][3], a0,a1,a2,a3, bl0,bl1);
                MMA_BF16(acc[mi][1][0],acc[mi][1][1],acc[mi][1][2],acc[mi][1][3], a0,a1,a2,a3, bl2,bl3);
                MMA_BF16(acc[mi][2][0],acc[mi][2][1],acc[mi][2][2],acc[mi][2][3], a0,a1,a2,a3, bl4,bl5);
                MMA_BF16(acc[mi][3][0],acc[mi][3][1],acc[mi][3][2],acc[mi][3][3], a0,a1,a2,a3, bl6,bl7);
            }
#pragma unroll
            for (int mi = 0; mi < 4; mi++) {
                uint32_t a0, a1, a2, a3;
                uint32_t aa = sAlo + (wm + mi*16 + laneA_row) * RS_A + laneA_half + koffA;
                LDM_X4(a0, a1, a2, a3, aa);
                MMA_BF16(acc[mi][0][0],acc[mi][0][1],acc[mi][0][2],acc[mi][0][3], a0,a1,a2,a3, bh0,bh1);
                MMA_BF16(acc[mi][1][0],acc[mi][1][1],acc[mi][1][2],acc[mi][1][3], a0,a1,a2,a3, bh2,bh3);
                MMA_BF16(acc[mi][2][0],acc[mi][2][1],acc[mi][2][2],acc[mi][2][3], a0,a1,a2,a3, bh4,bh5);
                MMA_BF16(acc[mi][3][0],acc[mi][3][1],acc[mi][3][2],acc[mi][3][3], a0,a1,a2,a3, bh6,bh7);
            }
        }
    }
#undef LOADC
#undef CP_A

    const int lane4 = lane >> 2, lane2 = (lane & 3) * 2;
#pragma unroll
    for (int mi = 0; mi < 4; mi++) {
        int r0 = bm + wm + mi*16 + lane4;
        int r1 = r0 + 8;
#pragma unroll
        for (int ni = 0; ni < 4; ni++) {
            int ng = bn + wn + ni*8 + lane2;
            float bz0 = bias[ng], bz1 = bias[ng + 1];
            float c0 = acc[mi][ni][0] + bz0, c1 = acc[mi][ni][1] + bz1;
            float c2 = acc[mi][ni][2] + bz0, c3 = acc[mi][ni][3] + bz1;
            if (MODE == 1) {
                float2 v0 = {c0, c1}, v1 = {c2, c3};
                *(float2*)&outp[(long)r0 * NC + ng] = v0;
                *(float2*)&outp[(long)r1 * NC + ng] = v1;
            } else {
                const int sel = bn >> 10;
                int n = ng & (NC - 1);
                int head = n >> 6, dh = n & (DHD - 1);
                int b0 = r0 >> 11, t0 = r0 & (NT - 1);
                int b1 = r1 >> 11, t1 = r1 & (NT - 1);
                long e0 = ((long)(((b0 << 4) + head) * NT + t0)) * DHD + dh;
                long e1 = ((long)(((b1 << 4) + head) * NT + t1)) * DHD + dh;
                if (sel == 2) {   // V: single fp16 term
                    uint32_t hv0, hv1;
                    CVT_F16X2(c0, c1, hv0);
                    CVT_F16X2(c2, c3, hv1);
                    *(uint32_t*)(g_vhi + e0) = hv0;
                    *(uint32_t*)(g_vhi + e1) = hv1;
                } else {
                    if (sel == 0) {
                        const float qs = 0.125f * LOG2E;
                        c0 *= qs; c1 *= qs; c2 *= qs; c3 *= qs;
                    }
                    uint32_t hi0, lo0, hi1, lo1;
                    CVT_HILO(c0, c1, hi0, lo0);
                    CVT_HILO(c2, c3, hi1, lo1);
                    __nv_bfloat16* dhi = (sel == 0) ? g_qhi : g_khi;
                    __nv_bfloat16* dlo = (sel == 0) ? g_qlo : g_klo;
                    *(uint32_t*)(dhi + e0) = hi0;  *(uint32_t*)(dlo + e0) = lo0;
                    *(uint32_t*)(dhi + e1) = hi1;  *(uint32_t*)(dlo + e1) = lo1;
                }
            }
        }
    }
}

// ---------------- tensor-core flash attention: fp16 PV single-term V ------------
#define RS_F 144
#define QTILE_B (256 * RS_F)
#define KVT_B   (64 * RS_F)
#define STAGE_F (4 * KVT_B)
#define OFF_Q    0
#define OFF_ST   (2 * QTILE_B)
#define OFF_BAND (OFF_ST + 2 * STAGE_F)
#define FL_SMEM  (OFF_BAND + 2 * 336 * 8)

__global__ void __launch_bounds__(512, 1) flash_kernel()
{
    extern __shared__ __align__(16) char fsm[];
    const int tid = threadIdx.x, wid = tid >> 5, lane = tid & 31;
    const int bh = blockIdx.y, h = bh & (NH - 1), b = bh >> 4;
    const int q0 = blockIdx.x * 256;
    const uint32_t sb = s2u(fsm);
    const long kvbase = (long)bh * NT * DHD;
    const int hb = h * NDIST;
    float2* bandp = (float2*)(fsm + OFF_BAND);

    {
        int a = tid >> 8, row = tid & 255;
        const uint4* src = (const uint4*)((a ? g_qlo : g_qhi) + kvbase + (long)(q0 + row) * DHD);
        uint4* dst = (uint4*)(fsm + OFF_Q + a * QTILE_B + row * RS_F);
#pragma unroll
        for (int u = 0; u < 8; u++) dst[u] = src[u];
    }

// groups: 0=khi, 1=klo, 2=vhi (group 3 idle - vlo unused)
#define CP_STAGE(tile, buf) do { \
    int a_ = tid >> 7; int r2_ = tid & 127; int row_ = r2_ >> 1; \
    if (a_ < 3) { \
        const __nv_bfloat16* g_ = (a_ == 0) ? g_khi : (a_ == 1) ? g_klo : g_vhi; \
        const char* src_ = (const char*)(g_ + kvbase + (long)((tile) * 64 + row_) * DHD) + (r2_ & 1) * 64; \
        uint32_t dst_ = sb + OFF_ST + (buf) * STAGE_F + a_ * KVT_B + row_ * RS_F + (r2_ & 1) * 64; \
        CP_ASYNC16(dst_ +  0, src_ +  0); CP_ASYNC16(dst_ + 16, src_ + 16); \
        CP_ASYNC16(dst_ + 32, src_ + 32); CP_ASYNC16(dst_ + 48, src_ + 48); \
    } \
} while(0)

#define BAND_W(tile, buf) do { \
    int base_ = q0 - (tile) * 64 + 1984; \
    if (tid < 319) { \
        int d0_ = base_ + tid; int d1_ = d0_ - 1; if (d1_ < 0) d1_ = 0; \
        bandp[(buf) * 336 + tid] = make_float2(g_bias[hb + d0_], g_bias[hb + d1_]); \
    } \
} while(0)

    CP_STAGE(0, 0);
    CP_COMMIT();
    BAND_W(0, 0);

    float o[8][4];
#pragma unroll
    for (int nt = 0; nt < 8; nt++)
#pragma unroll
        for (int r = 0; r < 4; r++) o[nt][r] = 0.f;
    float rm0 = -1e30f, rm1 = -1e30f, rl0 = 0.f, rl1 = 0.f;

    const int g = lane >> 2, t2 = (lane & 3) * 2;
    const int krow_lane = ((lane >> 4) & 1) * 8 + (lane & 7);
    const int kbyte     = ((lane >> 3) & 1) * 16;
    const int vrow_lane = ((lane >> 3) & 1) * 8 + (lane & 7);
    const int vcol      = (lane >> 4);
    const int qrow_lane = lane & 15;
    const int qbyte     = (lane >> 4) * 16;
    const int e0 = wid * 16 + g + 63 - t2;

    for (int i = 0; i < 32; i++) {
        const int buf = i & 1;
        CP_WAIT0();
        __syncthreads();
        if (i + 1 < 32) {
            CP_STAGE(i + 1, buf ^ 1);
            CP_COMMIT();
            BAND_W(i + 1, buf ^ 1);
        }

        const uint32_t stg  = sb + OFF_ST + buf * STAGE_F;
        const uint32_t sKhi = stg;
        const uint32_t sVhi = stg + 2 * KVT_B;

        float s[8][4];
#pragma unroll
        for (int nt = 0; nt < 8; nt++)
#pragma unroll
            for (int r = 0; r < 4; r++) s[nt][r] = 0.f;

#pragma unroll
        for (int kt = 0; kt < 4; kt++) {
            uint32_t qh0, qh1, qh2, qh3, ql0, ql1, ql2, ql3;
            uint32_t qa = sb + OFF_Q + (wid*16 + qrow_lane) * RS_F + qbyte + kt * 32;
            LDM_X4(qh0, qh1, qh2, qh3, qa);
            LDM_X4(ql0, ql1, ql2, ql3, qa + QTILE_B);
#pragma unroll
            for (int p = 0; p < 4; p++) {
                uint32_t k0,k1,k2,k3, n0,n1,n2,n3;
                uint32_t ka = sKhi + (p*16 + krow_lane) * RS_F + kbyte + kt * 32;
                LDM_X4(k0, k1, k2, k3, ka);
                LDM_X4(n0, n1, n2, n3, ka + KVT_B);
                MMA_BF16(s[2*p][0],s[2*p][1],s[2*p][2],s[2*p][3],
                         qh0,qh1,qh2,qh3, k0,k1);
                MMA_BF16(s[2*p][0],s[2*p][1],s[2*p][2],s[2*p][3],
                         qh0,qh1,qh2,qh3, n0,n1);
                MMA_BF16(s[2*p][0],s[2*p][1],s[2*p][2],s[2*p][3],
                         ql0,ql1,ql2,ql3, k0,k1);
                MMA_BF16(s[2*p+1][0],s[2*p+1][1],s[2*p+1][2],s[2*p+1][3],
                         qh0,qh1,qh2,qh3, k2,k3);
                MMA_BF16(s[2*p+1][0],s[2*p+1][1],s[2*p+1][2],s[2*p+1][3],
                         qh0,qh1,qh2,qh3, n2,n3);
                MMA_BF16(s[2*p+1][0],s[2*p+1][1],s[2*p+1][2],s[2*p+1][3],
                         ql0,ql1,ql2,ql3, k2,k3);
            }
        }

        const float2* bd = bandp + buf * 336;
        float mx0 = -1e30f, mx1 = -1e30f;
#pragma unroll
        for (int nt = 0; nt < 8; nt++) {
            float2 b0v = bd[e0 - 8*nt];
            float2 b1v = bd[e0 + 8 - 8*nt];
            s[nt][0] += b0v.x;  s[nt][1] += b0v.y;
            s[nt][2] += b1v.x;  s[nt][3] += b1v.y;
            mx0 = fmaxf(mx0, fmaxf(s[nt][0], s[nt][1]));
            mx1 = fmaxf(mx1, fmaxf(s[nt][2], s[nt][3]));
        }
        mx0 = fmaxf(mx0, __shfl_xor_sync(0xffffffffu, mx0, 1));
        mx0 = fmaxf(mx0, __shfl_xor_sync(0xffffffffu, mx0, 2));
        mx1 = fmaxf(mx1, __shfl_xor_sync(0xffffffffu, mx1, 1));
        mx1 = fmaxf(mx1, __shfl_xor_sync(0xffffffffu, mx1, 2));
        float mn0 = fmaxf(rm0, mx0), mn1 = fmaxf(rm1, mx1);
        float a0 = rm0 - mn0, a1 = rm1 - mn1;
        float sc0, sc1;
        EX2(sc0, a0);
        EX2(sc1, a1);
        float su0 = 0.f, su1 = 0.f;
#pragma unroll
        for (int nt = 0; nt < 8; nt++) {
            float d0 = s[nt][0] - mn0, d1 = s[nt][1] - mn0;
            float d2 = s[nt][2] - mn1, d3 = s[nt][3] - mn1;
            EX2(s[nt][0], d0);
            EX2(s[nt][1], d1);
            EX2(s[nt][2], d2);
            EX2(s[nt][3], d3);
            su0 += s[nt][0] + s[nt][1];
            su1 += s[nt][2] + s[nt][3];
        }
        su0 += __shfl_xor_sync(0xffffffffu, su0, 1);
        su0 += __shfl_xor_sync(0xffffffffu, su0, 2);
        su1 += __shfl_xor_sync(0xffffffffu, su1, 1);
        su1 += __shfl_xor_sync(0xffffffffu, su1, 2);
        rl0 = rl0 * sc0 + su0;  rm0 = mn0;
        rl1 = rl1 * sc1 + su1;  rm1 = mn1;
#pragma unroll
        for (int nt = 0; nt < 8; nt++) {
            o[nt][0] *= sc0; o[nt][1] *= sc0;
            o[nt][2] *= sc1; o[nt][3] *= sc1;
        }

        // ---- O += P V : P fp16, V single fp16 term ----
#pragma unroll
        for (int st = 0; st < 4; st++) {
            uint32_t p0, p1, p2r, p3;
            CVT_F16X2(s[2*st][0],   s[2*st][1],   p0);
            CVT_F16X2(s[2*st][2],   s[2*st][3],   p1);
            CVT_F16X2(s[2*st+1][0], s[2*st+1][1], p2r);
            CVT_F16X2(s[2*st+1][2], s[2*st+1][3], p3);
#pragma unroll
            for (int p2 = 0; p2 < 4; p2++) {
                uint32_t v0,v1,v2,v3;
                uint32_t va = sVhi + (st*16 + vrow_lane) * RS_F + (p2*2 + vcol) * 16;
                LDM_X4T(v0, v1, v2, v3, va);
                MMA_F16(o[2*p2][0],o[2*p2][1],o[2*p2][2],o[2*p2][3],
                        p0,p1,p2r,p3, v0,v1);
                MMA_F16(o[2*p2+1][0],o[2*p2+1][1],o[2*p2+1][2],o[2*p2+1][3],
                        p0,p1,p2r,p3, v2,v3);
            }
        }
    }

    // ---- normalize + write ctx as bf16 hi/lo into g_ctx scratch ----
    {
        __nv_bfloat16* chi = (__nv_bfloat16*)g_ctx;
        __nv_bfloat16* clo = chi + (long)NM * NC;
        float inv0 = 1.f / rl0, inv1 = 1.f / rl1;
        int t0 = q0 + wid*16 + g, t1 = t0 + 8;
        long ce0 = (long)(b * NT + t0) * NC + h * DHD + t2;
        long ce1 = (long)(b * NT + t1) * NC + h * DHD + t2;
#pragma unroll
        for (int nt = 0; nt < 8; nt++) {
            uint32_t hi, lo;
            CVT_HILO(o[nt][0] * inv0, o[nt][1] * inv0, hi, lo);
            *(uint32_t*)(chi + ce0 + nt*8) = hi;
            *(uint32_t*)(clo + ce0 + nt*8) = lo;
            CVT_HILO(o[nt][2] * inv1, o[nt][3] * inv1, hi, lo);
            *(uint32_t*)(chi + ce1 + nt*8) = hi;
            *(uint32_t*)(clo + ce1 + nt*8) = lo;
        }
    }
#undef CP_STAGE
#undef BAND_W
}

// ---------------- launch ---------------------------------------------------------
extern "C" void kernel_launch(void* const* d_in, const int* in_sizes, int n_in,
                              void* d_out, int out_size)
{
    const float* x     = (const float*)d_in[0];
    const float* w_qkv = (const float*)d_in[1];
    const float* b_qkv = (const float*)d_in[2];
    const float* w_out = (const float*)d_in[3];
    const float* b_out = (const float*)d_in[4];
    const float* w1    = (const float*)d_in[5];
    const float* b1    = (const float*)d_in[6];
    const float* w2    = (const float*)d_in[7];
    const float* b2    = (const float*)d_in[8];
    float* out = (float*)d_out;

    cudaFuncSetAttribute(flash_kernel, cudaFuncAttributeMaxDynamicSharedMemorySize,
                         FL_SMEM);
    cudaFuncSetAttribute(mm_kernel<0>, cudaFuncAttributeMaxDynamicSharedMemorySize,
                         MM_SMEM_BYTES);
    cudaFuncSetAttribute(mm_kernel<1>, cudaFuncAttributeMaxDynamicSharedMemorySize,
                         MM_SMEM_BYTES);

    rpe_kernel<<<(NDIST + 255) / 256, 256>>>(w1, b1, w2, b2);

    conv_x_kernel<<<NM * NC / 4 / 256, 256>>>(x);

    {   // QKV projection
        dim3 gq(N3C / BN, NM / BM);
        mm_kernel<0><<<gq, 256, MM_SMEM_BYTES>>>(w_qkv, N3C, b_qkv, nullptr);
    }
    {   // flash attention (writes ctx bf16 hi/lo into g_ctx scratch)
        dim3 gf(NT / 256, NB * NH);
        flash_kernel<<<gf, 512, FL_SMEM>>>();
    }
    {   // output projection (A = ctx bf16 via cp.async)
        dim3 go(NC / BN, NM / BM);
        mm_kernel<1><<<go, 256, MM_SMEM_BYTES>>>(w_out, NC, b_out, out);
    }
}

// round 16
// speedup vs baseline: 1.2439x; 1.1176x over previous
#include <cuda_runtime.h>
#include <cuda_bf16.h>
#include <cuda_fp16.h>
#include <math.h>
#include <stdint.h>

#define NB 2
#define NT 2048
#define NC 1024
#define NH 16
#define DHD 64
#define NHID 32
#define N3C 3072
#define NM 4096
#define NDIST 4095
#define MMK 1024
#define BM 128
#define BN 128
#define BKC 32
#define NCHUNK (MMK/BKC)
#define LOG2E 1.4426950408889634f

// ---------------- statics: same 67.2MB footprint as passing R6-R15 ---------------
__device__ __align__(16) __nv_bfloat16 g_qhi[NB*NH*NT*DHD];  // bf16, pre-scaled log2e/8
__device__ __align__(16) __nv_bfloat16 g_qlo[NB*NH*NT*DHD];
__device__ __align__(16) __nv_bfloat16 g_khi[NB*NH*NT*DHD];
__device__ __align__(16) __nv_bfloat16 g_klo[NB*NH*NT*DHD];
__device__ __align__(16) __nv_bfloat16 g_vhi[NB*NH*NT*DHD];  // fp16 (single-term V)
__device__ __align__(16) __nv_bfloat16 g_vlo[NB*NH*NT*DHD];  // unused (kept for footprint)
// g_ctx region: (a) x fp16 hi/lo scratch for mm<0>; (b) ctx fp16 hi/lo (flash -> mm<1>)
__device__ __align__(16) float g_ctx[NM*NC];
__device__ float g_bias[NH*NDIST];          // pre-scaled by log2e

// ================= PTX helpers ==================================================
__device__ __forceinline__ uint32_t s2u(const void* p) {
    uint32_t a;
    asm("{ .reg .u64 t; cvta.to.shared.u64 t, %1; cvt.u32.u64 %0, t; }" : "=r"(a) : "l"(p));
    return a;
}
#define CP_ASYNC16(dst, src) \
    asm volatile("cp.async.cg.shared.global [%0], [%1], 16;" :: "r"(dst), "l"(src))
#define CP_COMMIT() asm volatile("cp.async.commit_group;" ::: "memory")
#define CP_WAIT0()  asm volatile("cp.async.wait_group 0;" ::: "memory")

#define LDM_X4(r0,r1,r2,r3,addr) \
    asm volatile("ldmatrix.sync.aligned.m8n8.x4.shared.b16 {%0,%1,%2,%3}, [%4];" \
        : "=r"(r0),"=r"(r1),"=r"(r2),"=r"(r3) : "r"(addr))
#define LDM_X4T(r0,r1,r2,r3,addr) \
    asm volatile("ldmatrix.sync.aligned.m8n8.x4.trans.shared.b16 {%0,%1,%2,%3}, [%4];" \
        : "=r"(r0),"=r"(r1),"=r"(r2),"=r"(r3) : "r"(addr))
#define LDM_X2T(r0,r1,addr) \
    asm volatile("ldmatrix.sync.aligned.m8n8.x2.trans.shared.b16 {%0,%1}, [%2];" \
        : "=r"(r0),"=r"(r1) : "r"(addr))

#define MMA_BF16(c0,c1,c2,c3,a0,a1,a2,a3,b0,b1) \
    asm volatile("mma.sync.aligned.m16n8k16.row.col.f32.bf16.bf16.f32 " \
                 "{%0,%1,%2,%3}, {%4,%5,%6,%7}, {%8,%9}, {%0,%1,%2,%3};" \
                 : "+f"(c0), "+f"(c1), "+f"(c2), "+f"(c3) \
                 : "r"(a0), "r"(a1), "r"(a2), "r"(a3), "r"(b0), "r"(b1))

#define MMA_F16(c0,c1,c2,c3,a0,a1,a2,a3,b0,b1) \
    asm volatile("mma.sync.aligned.m16n8k16.row.col.f32.f16.f16.f32 " \
                 "{%0,%1,%2,%3}, {%4,%5,%6,%7}, {%8,%9}, {%0,%1,%2,%3};" \
                 : "+f"(c0), "+f"(c1), "+f"(c2), "+f"(c3) \
                 : "r"(a0), "r"(a1), "r"(a2), "r"(a3), "r"(b0), "r"(b1))

#define CVT_HILO(x, y, hi, lo) do{ \
    asm("cvt.rn.bf16x2.f32 %0, %1, %2;" : "=r"(hi) : "f"(y), "f"(x)); \
    float _lx = (x) - __uint_as_float((hi) << 16); \
    float _ly = (y) - __uint_as_float((hi) & 0xFFFF0000u); \
    asm("cvt.rn.bf16x2.f32 %0, %1, %2;" : "=r"(lo) : "f"(_ly), "f"(_lx)); \
}while(0)

// fp16 hi/lo split (hi packs x->lo half, y->hi half)
#define CVT_HILO_F16(x, y, hi, lo) do{ \
    asm("cvt.rn.f16x2.f32 %0, %1, %2;" : "=r"(hi) : "f"(y), "f"(x)); \
    float _fx, _fy; \
    asm("{ .reg .f16 a, b; mov.b32 {a, b}, %2; cvt.f32.f16 %0, a; cvt.f32.f16 %1, b; }" \
        : "=f"(_fx), "=f"(_fy) : "r"(hi)); \
    float _lx = (x) - _fx, _ly = (y) - _fy; \
    asm("cvt.rn.f16x2.f32 %0, %1, %2;" : "=r"(lo) : "f"(_ly), "f"(_lx)); \
}while(0)

#define CVT_F16X2(x, y, d) \
    asm("cvt.rn.f16x2.f32 %0, %1, %2;" : "=r"(d) : "f"(y), "f"(x))

#define EX2(d, s) asm("ex2.approx.ftz.f32 %0, %1;" : "=f"(d) : "f"(s))

// ---------------- RPE bias table (pre-scaled by log2e) --------------------------
__global__ void rpe_kernel(const float* __restrict__ w1, const float* __restrict__ b1,
                           const float* __restrict__ w2, const float* __restrict__ b2)
{
    int d = blockIdx.x * blockDim.x + threadIdx.x;
    if (d >= NDIST) return;
    float rel = (float)(d - (NT - 1));
    float sgn = (rel > 0.f) ? 1.f : ((rel < 0.f) ? -1.f : 0.f);
    float x = sgn * log1pf(fabsf(rel));
    float h[NHID];
#pragma unroll
    for (int j = 0; j < NHID; j++)
        h[j] = fmaxf(fmaf(x, __ldg(&w1[j]), __ldg(&b1[j])), 0.f);
#pragma unroll
    for (int hd = 0; hd < NH; hd++) {
        float acc = __ldg(&b2[hd]);
#pragma unroll
        for (int j = 0; j < NHID; j++)
            acc = fmaf(h[j], __ldg(&w2[j*NH + hd]), acc);
        g_bias[hd*NDIST + d] = acc * LOG2E;
    }
}

// ---------------- x -> fp16 hi/lo (into g_ctx scratch) ---------------------------
__global__ void conv_x_kernel(const float* __restrict__ x) {
    __nv_bfloat16* xhi = (__nv_bfloat16*)g_ctx;
    __nv_bfloat16* xlo = xhi + (long)NM * NC;
    long i = (long)(blockIdx.x * blockDim.x + threadIdx.x) * 4;
    float4 v = *(const float4*)&x[i];
    uint32_t h01, l01, h23, l23;
    CVT_HILO_F16(v.x, v.y, h01, l01);
    CVT_HILO_F16(v.z, v.w, h23, l23);
    *(uint2*)&xhi[i] = make_uint2(h01, h23);
    *(uint2*)&xlo[i] = make_uint2(l01, l23);
}

// ---------------- 2-term fp16 GEMM, 256 threads ----------------------------------
// C = (Ah + Al) x B : A fp16 hi/lo (pre-converted, cp.async), B fp32 -> fp16 single
#define RS_A 80
#define A_TILE_B (128 * RS_A)
#define RS_B 272
#define B_TILE_B (32 * RS_B)
#define STAGE_B (2*A_TILE_B + B_TILE_B)      // 29184
#define OFF_AHI 0
#define OFF_ALO A_TILE_B
#define OFF_BHI (2*A_TILE_B)
#define MM_SMEM_BYTES (2 * STAGE_B)          // 58368

template<int MODE>
__global__ void __launch_bounds__(256, 1) mm_kernel(
    const float* __restrict__ Bin, int ldb,
    const float* __restrict__ bias, float* __restrict__ outp)
{
    extern __shared__ __align__(16) char dsm[];
    const __nv_bfloat16* __restrict__ Axhi = (const __nv_bfloat16*)g_ctx;
    const __nv_bfloat16* __restrict__ Axlo = Axhi + (long)NM * NC;

    const int tid = threadIdx.x;
    const int wid = tid >> 5, lane = tid & 31;
    const int bm = blockIdx.y * BM, bn = blockIdx.x * BN;
    const int wm = (wid & 1) * 64, wn = (wid >> 1) * 32;
    const uint32_t sbase = s2u(dsm);

    float acc[4][4][4];
#pragma unroll
    for (int mi = 0; mi < 4; mi++)
#pragma unroll
        for (int ni = 0; ni < 4; ni++)
#pragma unroll
            for (int r = 0; r < 4; r++) acc[mi][ni][r] = 0.f;

    const float* __restrict__ bptr = Bin + (long)(tid >> 3) * ldb + bn + (tid & 7) * 16;
    const int ar = tid >> 1, ah = tid & 1;

#define CP_A(chunk, stage) do { \
    long off_ = (long)(bm + ar) * MMK + (chunk) * BKC + ah * 16; \
    uint32_t d_ = sbase + (stage) * STAGE_B + ar * RS_A + ah * 32; \
    CP_ASYNC16(d_ + OFF_AHI,      Axhi + off_); \
    CP_ASYNC16(d_ + OFF_AHI + 16, Axhi + off_ + 8); \
    CP_ASYNC16(d_ + OFF_ALO,      Axlo + off_); \
    CP_ASYNC16(d_ + OFF_ALO + 16, Axlo + off_ + 8); \
    CP_COMMIT(); \
} while(0)

    float4 vb0, vb1, vb2, vb3;
#define LOADC(k0) do { \
    const float* _b = bptr + (long)(k0) * ldb; \
    vb0 = *(const float4*)(_b + 0);  vb1 = *(const float4*)(_b + 4); \
    vb2 = *(const float4*)(_b + 8);  vb3 = *(const float4*)(_b + 12); \
} while(0)

    CP_A(0, 0);
    LOADC(0);

    const int laneA_row = lane & 15, laneA_half = (lane >> 4) * 16;
    const uint32_t laneB_row = (lane & 7) + ((lane >> 3) & 1) * 8;

    for (int i = 0; i < NCHUNK; i++) {
        const int buf = i & 1;
        char* sp = dsm + buf * STAGE_B;
        {
            char* pb = sp + (tid >> 3) * RS_B + (tid & 7) * 32;
            uint32_t h0, h1, h2, h3, h4, h5, h6, h7;
            CVT_F16X2(vb0.x, vb0.y, h0);  CVT_F16X2(vb0.z, vb0.w, h1);
            CVT_F16X2(vb1.x, vb1.y, h2);  CVT_F16X2(vb1.z, vb1.w, h3);
            CVT_F16X2(vb2.x, vb2.y, h4);  CVT_F16X2(vb2.z, vb2.w, h5);
            CVT_F16X2(vb3.x, vb3.y, h6);  CVT_F16X2(vb3.z, vb3.w, h7);
            *(uint4*)(pb + OFF_BHI +  0) = make_uint4(h0, h1, h2, h3);
            *(uint4*)(pb + OFF_BHI + 16) = make_uint4(h4, h5, h6, h7);
        }
        CP_WAIT0();
        __syncthreads();
        // all threads finished MMA(i-1) (last reader of stage buf^1): safe to refill
        if (i + 1 < NCHUNK) { CP_A(i + 1, buf ^ 1); LOADC((i + 1) * BKC); }

        const uint32_t stb  = sbase + buf * STAGE_B;
        const uint32_t sAhi = stb + OFF_AHI;
        const uint32_t sAlo = stb + OFF_ALO;
        const uint32_t sBhi = stb + OFF_BHI;

#pragma unroll
        for (int kk = 0; kk < 2; kk++) {
            const uint32_t koffA = kk * 32;
            const uint32_t browB = (kk * 16 + laneB_row) * RS_B;
            uint32_t bh0,bh1,bh2,bh3,bh4,bh5,bh6,bh7;
            LDM_X2T(bh0, bh1, sBhi + browB + (wn + 0*8) * 2);
            LDM_X2T(bh2, bh3, sBhi + browB + (wn + 1*8) * 2);
            LDM_X2T(bh4, bh5, sBhi + browB + (wn + 2*8) * 2);
            LDM_X2T(bh6, bh7, sBhi + browB + (wn + 3*8) * 2);
#pragma unroll
            for (int mi = 0; mi < 4; mi++) {
                uint32_t a0, a1, a2, a3;
                uint32_t aa = sAhi + (wm + mi*16 + laneA_row) * RS_A + laneA_half + koffA;
                LDM_X4(a0, a1, a2, a3, aa);
                MMA_F16(acc[mi][0][0],acc[mi][0][1],acc[mi][0][2],acc[mi][0][3], a0,a1,a2,a3, bh0,bh1);
                MMA_F16(acc[mi][1][0],acc[mi][1][1],acc[mi][1][2],acc[mi][1][3], a0,a1,a2,a3, bh2,bh3);
                MMA_F16(acc[mi][2][0],acc[mi][2][1],acc[mi][2][2],acc[mi][2][3], a0,a1,a2,a3, bh4,bh5);
                MMA_F16(acc[mi][3][0],acc[mi][3][1],acc[mi][3][2],acc[mi][3][3], a0,a1,a2,a3, bh6,bh7);
            }
#pragma unroll
            for (int mi = 0; mi < 4; mi++) {
                uint32_t a0, a1, a2, a3;
                uint32_t aa = sAlo + (wm + mi*16 + laneA_row) * RS_A + laneA_half + koffA;
                LDM_X4(a0, a1, a2, a3, aa);
                MMA_F16(acc[mi][0][0],acc[mi][0][1],acc[mi][0][2],acc[mi][0][3], a0,a1,a2,a3, bh0,bh1);
                MMA_F16(acc[mi][1][0],acc[mi][1][1],acc[mi][1][2],acc[mi][1][3], a0,a1,a2,a3, bh2,bh3);
                MMA_F16(acc[mi][2][0],acc[mi][2][1],acc[mi][2][2],acc[mi][2][3], a0,a1,a2,a3, bh4,bh5);
                MMA_F16(acc[mi][3][0],acc[mi][3][1],acc[mi][3][2],acc[mi][3][3], a0,a1,a2,a3, bh6,bh7);
            }
        }
    }
#undef LOADC
#undef CP_A

    const int lane4 = lane >> 2, lane2 = (lane & 3) * 2;
#pragma unroll
    for (int mi = 0; mi < 4; mi++) {
        int r0 = bm + wm + mi*16 + lane4;
        int r1 = r0 + 8;
#pragma unroll
        for (int ni = 0; ni < 4; ni++) {
            int ng = bn + wn + ni*8 + lane2;
            float bz0 = bias[ng], bz1 = bias[ng + 1];
            float c0 = acc[mi][ni][0] + bz0, c1 = acc[mi][ni][1] + bz1;
            float c2 = acc[mi][ni][2] + bz0, c3 = acc[mi][ni][3] + bz1;
            if (MODE == 1) {
                float2 v0 = {c0, c1}, v1 = {c2, c3};
                *(float2*)&outp[(long)r0 * NC + ng] = v0;
                *(float2*)&outp[(long)r1 * NC + ng] = v1;
            } else {
                const int sel = bn >> 10;
                int n = ng & (NC - 1);
                int head = n >> 6, dh = n & (DHD - 1);
                int b0 = r0 >> 11, t0 = r0 & (NT - 1);
                int b1 = r1 >> 11, t1 = r1 & (NT - 1);
                long e0 = ((long)(((b0 << 4) + head) * NT + t0)) * DHD + dh;
                long e1 = ((long)(((b1 << 4) + head) * NT + t1)) * DHD + dh;
                if (sel == 2) {   // V: single fp16 term
                    uint32_t hv0, hv1;
                    CVT_F16X2(c0, c1, hv0);
                    CVT_F16X2(c2, c3, hv1);
                    *(uint32_t*)(g_vhi + e0) = hv0;
                    *(uint32_t*)(g_vhi + e1) = hv1;
                } else {          // Q/K: bf16 hi/lo (3-term S in flash)
                    if (sel == 0) {
                        const float qs = 0.125f * LOG2E;
                        c0 *= qs; c1 *= qs; c2 *= qs; c3 *= qs;
                    }
                    uint32_t hi0, lo0, hi1, lo1;
                    CVT_HILO(c0, c1, hi0, lo0);
                    CVT_HILO(c2, c3, hi1, lo1);
                    __nv_bfloat16* dhi = (sel == 0) ? g_qhi : g_khi;
                    __nv_bfloat16* dlo = (sel == 0) ? g_qlo : g_klo;
                    *(uint32_t*)(dhi + e0) = hi0;  *(uint32_t*)(dlo + e0) = lo0;
                    *(uint32_t*)(dhi + e1) = hi1;  *(uint32_t*)(dlo + e1) = lo1;
                }
            }
        }
    }
}

// ---------------- tensor-core flash attention: fp16 PV single-term V ------------
#define RS_F 144
#define QTILE_B (256 * RS_F)
#define KVT_B   (64 * RS_F)
#define STAGE_F (4 * KVT_B)
#define OFF_Q    0
#define OFF_ST   (2 * QTILE_B)
#define OFF_BAND (OFF_ST + 2 * STAGE_F)
#define FL_SMEM  (OFF_BAND + 2 * 336 * 8)

__global__ void __launch_bounds__(512, 1) flash_kernel()
{
    extern __shared__ __align__(16) char fsm[];
    const int tid = threadIdx.x, wid = tid >> 5, lane = tid & 31;
    const int bh = blockIdx.y, h = bh & (NH - 1), b = bh >> 4;
    const int q0 = blockIdx.x * 256;
    const uint32_t sb = s2u(fsm);
    const long kvbase = (long)bh * NT * DHD;
    const int hb = h * NDIST;
    float2* bandp = (float2*)(fsm + OFF_BAND);

    {
        int a = tid >> 8, row = tid & 255;
        const uint4* src = (const uint4*)((a ? g_qlo : g_qhi) + kvbase + (long)(q0 + row) * DHD);
        uint4* dst = (uint4*)(fsm + OFF_Q + a * QTILE_B + row * RS_F);
#pragma unroll
        for (int u = 0; u < 8; u++) dst[u] = src[u];
    }

// groups: 0=khi, 1=klo, 2=vhi (group 3 idle)
#define CP_STAGE(tile, buf) do { \
    int a_ = tid >> 7; int r2_ = tid & 127; int row_ = r2_ >> 1; \
    if (a_ < 3) { \
        const __nv_bfloat16* g_ = (a_ == 0) ? g_khi : (a_ == 1) ? g_klo : g_vhi; \
        const char* src_ = (const char*)(g_ + kvbase + (long)((tile) * 64 + row_) * DHD) + (r2_ & 1) * 64; \
        uint32_t dst_ = sb + OFF_ST + (buf) * STAGE_F + a_ * KVT_B + row_ * RS_F + (r2_ & 1) * 64; \
        CP_ASYNC16(dst_ +  0, src_ +  0); CP_ASYNC16(dst_ + 16, src_ + 16); \
        CP_ASYNC16(dst_ + 32, src_ + 32); CP_ASYNC16(dst_ + 48, src_ + 48); \
    } \
} while(0)

#define BAND_W(tile, buf) do { \
    int base_ = q0 - (tile) * 64 + 1984; \
    if (tid < 319) { \
        int d0_ = base_ + tid; int d1_ = d0_ - 1; if (d1_ < 0) d1_ = 0; \
        bandp[(buf) * 336 + tid] = make_float2(g_bias[hb + d0_], g_bias[hb + d1_]); \
    } \
} while(0)

    CP_STAGE(0, 0);
    CP_COMMIT();
    BAND_W(0, 0);

    float o[8][4];
#pragma unroll
    for (int nt = 0; nt < 8; nt++)
#pragma unroll
        for (int r = 0; r < 4; r++) o[nt][r] = 0.f;
    float rm0 = -1e30f, rm1 = -1e30f, rl0 = 0.f, rl1 = 0.f;

    const int g = lane >> 2, t2 = (lane & 3) * 2;
    const int krow_lane = ((lane >> 4) & 1) * 8 + (lane & 7);
    const int kbyte     = ((lane >> 3) & 1) * 16;
    const int vrow_lane = ((lane >> 3) & 1) * 8 + (lane & 7);
    const int vcol      = (lane >> 4);
    const int qrow_lane = lane & 15;
    const int qbyte     = (lane >> 4) * 16;
    const int e0 = wid * 16 + g + 63 - t2;

    for (int i = 0; i < 32; i++) {
        const int buf = i & 1;
        CP_WAIT0();
        __syncthreads();
        if (i + 1 < 32) {
            CP_STAGE(i + 1, buf ^ 1);
            CP_COMMIT();
            BAND_W(i + 1, buf ^ 1);
        }

        const uint32_t stg  = sb + OFF_ST + buf * STAGE_F;
        const uint32_t sKhi = stg;
        const uint32_t sVhi = stg + 2 * KVT_B;

        float s[8][4];
#pragma unroll
        for (int nt = 0; nt < 8; nt++)
#pragma unroll
            for (int r = 0; r < 4; r++) s[nt][r] = 0.f;

#pragma unroll
        for (int kt = 0; kt < 4; kt++) {
            uint32_t qh0, qh1, qh2, qh3, ql0, ql1, ql2, ql3;
            uint32_t qa = sb + OFF_Q + (wid*16 + qrow_lane) * RS_F + qbyte + kt * 32;
            LDM_X4(qh0, qh1, qh2, qh3, qa);
            LDM_X4(ql0, ql1, ql2, ql3, qa + QTILE_B);
#pragma unroll
            for (int p = 0; p < 4; p++) {
                uint32_t k0,k1,k2,k3, n0,n1,n2,n3;
                uint32_t ka = sKhi + (p*16 + krow_lane) * RS_F + kbyte + kt * 32;
                LDM_X4(k0, k1, k2, k3, ka);
                LDM_X4(n0, n1, n2, n3, ka + KVT_B);
                MMA_BF16(s[2*p][0],s[2*p][1],s[2*p][2],s[2*p][3],
                         qh0,qh1,qh2,qh3, k0,k1);
                MMA_BF16(s[2*p][0],s[2*p][1],s[2*p][2],s[2*p][3],
                         qh0,qh1,qh2,qh3, n0,n1);
                MMA_BF16(s[2*p][0],s[2*p][1],s[2*p][2],s[2*p][3],
                         ql0,ql1,ql2,ql3, k0,k1);
                MMA_BF16(s[2*p+1][0],s[2*p+1][1],s[2*p+1][2],s[2*p+1][3],
                         qh0,qh1,qh2,qh3, k2,k3);
                MMA_BF16(s[2*p+1][0],s[2*p+1][1],s[2*p+1][2],s[2*p+1][3],
                         qh0,qh1,qh2,qh3, n2,n3);
                MMA_BF16(s[2*p+1][0],s[2*p+1][1],s[2*p+1][2],s[2*p+1][3],
                         ql0,ql1,ql2,ql3, k2,k3);
            }
        }

        const float2* bd = bandp + buf * 336;
        float mx0 = -1e30f, mx1 = -1e30f;
#pragma unroll
        for (int nt = 0; nt < 8; nt++) {
            float2 b0v = bd[e0 - 8*nt];
            float2 b1v = bd[e0 + 8 - 8*nt];
            s[nt][0] += b0v.x;  s[nt][1] += b0v.y;
            s[nt][2] += b1v.x;  s[nt][3] += b1v.y;
            mx0 = fmaxf(mx0, fmaxf(s[nt][0], s[nt][1]));
            mx1 = fmaxf(mx1, fmaxf(s[nt][2], s[nt][3]));
        }
        mx0 = fmaxf(mx0, __shfl_xor_sync(0xffffffffu, mx0, 1));
        mx0 = fmaxf(mx0, __shfl_xor_sync(0xffffffffu, mx0, 2));
        mx1 = fmaxf(mx1, __shfl_xor_sync(0xffffffffu, mx1, 1));
        mx1 = fmaxf(mx1, __shfl_xor_sync(0xffffffffu, mx1, 2));
        float mn0 = fmaxf(rm0, mx0), mn1 = fmaxf(rm1, mx1);
        float a0 = rm0 - mn0, a1 = rm1 - mn1;
        float sc0, sc1;
        EX2(sc0, a0);
        EX2(sc1, a1);
        float su0 = 0.f, su1 = 0.f;
#pragma unroll
        for (int nt = 0; nt < 8; nt++) {
            float d0 = s[nt][0] - mn0, d1 = s[nt][1] - mn0;
            float d2 = s[nt][2] - mn1, d3 = s[nt][3] - mn1;
            EX2(s[nt][0], d0);
            EX2(s[nt][1], d1);
            EX2(s[nt][2], d2);
            EX2(s[nt][3], d3);
            su0 += s[nt][0] + s[nt][1];
            su1 += s[nt][2] + s[nt][3];
        }
        su0 += __shfl_xor_sync(0xffffffffu, su0, 1);
        su0 += __shfl_xor_sync(0xffffffffu, su0, 2);
        su1 += __shfl_xor_sync(0xffffffffu, su1, 1);
        su1 += __shfl_xor_sync(0xffffffffu, su1, 2);
        rl0 = rl0 * sc0 + su0;  rm0 = mn0;
        rl1 = rl1 * sc1 + su1;  rm1 = mn1;
#pragma unroll
        for (int nt = 0; nt < 8; nt++) {
            o[nt][0] *= sc0; o[nt][1] *= sc0;
            o[nt][2] *= sc1; o[nt][3] *= sc1;
        }

        // ---- O += P V : P fp16, V single fp16 term ----
#pragma unroll
        for (int st = 0; st < 4; st++) {
            uint32_t p0, p1, p2r, p3;
            CVT_F16X2(s[2*st][0],   s[2*st][1],   p0);
            CVT_F16X2(s[2*st][2],   s[2*st][3],   p1);
            CVT_F16X2(s[2*st+1][0], s[2*st+1][1], p2r);
            CVT_F16X2(s[2*st+1][2], s[2*st+1][3], p3);
#pragma unroll
            for (int p2 = 0; p2 < 4; p2++) {
                uint32_t v0,v1,v2,v3;
                uint32_t va = sVhi + (st*16 + vrow_lane) * RS_F + (p2*2 + vcol) * 16;
                LDM_X4T(v0, v1, v2, v3, va);
                MMA_F16(o[2*p2][0],o[2*p2][1],o[2*p2][2],o[2*p2][3],
                        p0,p1,p2r,p3, v0,v1);
                MMA_F16(o[2*p2+1][0],o[2*p2+1][1],o[2*p2+1][2],o[2*p2+1][3],
                        p0,p1,p2r,p3, v2,v3);
            }
        }
    }

    // ---- normalize + write ctx as fp16 hi/lo into g_ctx scratch ----
    {
        __nv_bfloat16* chi = (__nv_bfloat16*)g_ctx;
        __nv_bfloat16* clo = chi + (long)NM * NC;
        float inv0 = 1.f / rl0, inv1 = 1.f / rl1;
        int t0 = q0 + wid*16 + g, t1 = t0 + 8;
        long ce0 = (long)(b * NT + t0) * NC + h * DHD + t2;
        long ce1 = (long)(b * NT + t1) * NC + h * DHD + t2;
#pragma unroll
        for (int nt = 0; nt < 8; nt++) {
            uint32_t hi, lo;
            CVT_HILO_F16(o[nt][0] * inv0, o[nt][1] * inv0, hi, lo);
            *(uint32_t*)(chi + ce0 + nt*8) = hi;
            *(uint32_t*)(clo + ce0 + nt*8) = lo;
            CVT_HILO_F16(o[nt][2] * inv1, o[nt][3] * inv1, hi, lo);
            *(uint32_t*)(chi + ce1 + nt*8) = hi;
            *(uint32_t*)(clo + ce1 + nt*8) = lo;
        }
    }
#undef CP_STAGE
#undef BAND_W
}

// ---------------- launch ---------------------------------------------------------
extern "C" void kernel_launch(void* const* d_in, const int* in_sizes, int n_in,
                              void* d_out, int out_size)
{
    const float* x     = (const float*)d_in[0];
    const float* w_qkv = (const float*)d_in[1];
    const float* b_qkv = (const float*)d_in[2];
    const float* w_out = (const float*)d_in[3];
    const float* b_out = (const float*)d_in[4];
    const float* w1    = (const float*)d_in[5];
    const float* b1    = (const float*)d_in[6];
    const float* w2    = (const float*)d_in[7];
    const float* b2    = (const float*)d_in[8];
    float* out = (float*)d_out;

    cudaFuncSetAttribute(flash_kernel, cudaFuncAttributeMaxDynamicSharedMemorySize,
                         FL_SMEM);
    cudaFuncSetAttribute(mm_kernel<0>, cudaFuncAttributeMaxDynamicSharedMemorySize,
                         MM_SMEM_BYTES);
    cudaFuncSetAttribute(mm_kernel<1>, cudaFuncAttributeMaxDynamicSharedMemorySize,
                         MM_SMEM_BYTES);

    rpe_kernel<<<(NDIST + 255) / 256, 256>>>(w1, b1, w2, b2);

    conv_x_kernel<<<NM * NC / 4 / 256, 256>>>(x);

    {   // QKV projection (2-term fp16)
        dim3 gq(N3C / BN, NM / BM);
        mm_kernel<0><<<gq, 256, MM_SMEM_BYTES>>>(w_qkv, N3C, b_qkv, nullptr);
    }
    {   // flash attention
        dim3 gf(NT / 256, NB * NH);
        flash_kernel<<<gf, 512, FL_SMEM>>>();
    }
    {   // output projection (2-term fp16)
        dim3 go(NC / BN, NM / BM);
        mm_kernel<1><<<go, 256, MM_SMEM_BYTES>>>(w_out, NC, b_out, out);
    }
}